// round 1
// baseline (speedup 1.0000x reference)
#include <cuda_runtime.h>

#define B_  8
#define T_  243
#define J_  17
#define H_  8
#define HD  64
#define C_  512
#define MROWS (B_*T_*J_)            // 33048
#define QS  (B_*H_*J_*T_*HD)        // 16920576  (== MROWS*512)

// scratch: qkv in [3][B][H][J][T][hd], attention output in [B][T][J][C]
__device__ float g_qkv[3*QS];
__device__ float g_att[QS];

// ---------------------------------------------------------------------------
// Tiled fp32 SGEMM, 128x128 tile, BK=8, 256 threads, 8x8 per thread.
// mode 0: C = x @ W_qkv scattered into g_qkv (q/k/v layout)
// mode 1: C = g_att @ W_proj + bias -> Cout
// ---------------------------------------------------------------------------
__global__ __launch_bounds__(256) void sgemm_kernel(
    const float* __restrict__ Ain, const float* __restrict__ Bm,
    const float* __restrict__ bias, float* __restrict__ Cout,
    int M, int N, int K, int mode)
{
    __shared__ float As[8][128];
    __shared__ float Bs[8][128];

    int tid  = threadIdx.x;
    int row0 = blockIdx.y * 128;
    int col0 = blockIdx.x * 128;

    const float* A = (mode == 1) ? g_att : Ain;

    int arow = tid >> 1;           // 0..127
    int acol = (tid & 1) << 2;     // 0 or 4
    int brow = tid >> 5;           // 0..7
    int bcol = (tid & 31) << 2;    // 0..124

    int tx = tid & 15;
    int ty = tid >> 4;

    float acc[8][8];
#pragma unroll
    for (int i = 0; i < 8; i++)
#pragma unroll
        for (int j = 0; j < 8; j++) acc[i][j] = 0.f;

    const float* Ap = A  + (size_t)(row0 + arow) * K + acol;
    const float* Bp = Bm + (size_t)brow * N + (col0 + bcol);
    bool aok = (row0 + arow) < M;

    for (int k0 = 0; k0 < K; k0 += 8) {
        float4 av = aok ? *(const float4*)Ap : make_float4(0.f, 0.f, 0.f, 0.f);
        float4 bv = *(const float4*)Bp;
        As[acol + 0][arow] = av.x;
        As[acol + 1][arow] = av.y;
        As[acol + 2][arow] = av.z;
        As[acol + 3][arow] = av.w;
        *(float4*)&Bs[brow][bcol] = bv;
        __syncthreads();
#pragma unroll
        for (int k = 0; k < 8; k++) {
            float4 a0 = *(const float4*)&As[k][ty * 8];
            float4 a1 = *(const float4*)&As[k][ty * 8 + 4];
            float4 b0 = *(const float4*)&Bs[k][tx * 8];
            float4 b1 = *(const float4*)&Bs[k][tx * 8 + 4];
            float ra[8] = {a0.x, a0.y, a0.z, a0.w, a1.x, a1.y, a1.z, a1.w};
            float rb[8] = {b0.x, b0.y, b0.z, b0.w, b1.x, b1.y, b1.z, b1.w};
#pragma unroll
            for (int i = 0; i < 8; i++)
#pragma unroll
                for (int j = 0; j < 8; j++)
                    acc[i][j] = fmaf(ra[i], rb[j], acc[i][j]);
        }
        __syncthreads();
        Ap += 8;
        Bp += (size_t)8 * N;
    }

    if (mode == 0) {
        // scatter into g_qkv[which][b][h][j][t][d]
#pragma unroll
        for (int i = 0; i < 8; i++) {
            int r = row0 + ty * 8 + i;
            if (r < M) {
                int b   = r / (T_ * J_);
                int rem = r - b * (T_ * J_);
                int t   = rem / J_;
                int jj  = rem - t * J_;
#pragma unroll
                for (int j = 0; j < 8; j++) {
                    int c = col0 + tx * 8 + j;
                    int which = c >> 9;          // /512
                    int h = (c >> 6) & 7;        // (c%512)/64
                    int d = c & 63;
                    size_t dst = (size_t)which * QS +
                        ((((size_t)(b * H_ + h) * J_ + jj) * T_ + t) * HD + d);
                    g_qkv[dst] = acc[i][j];
                }
            }
        }
    } else {
#pragma unroll
        for (int i = 0; i < 8; i++) {
            int r = row0 + ty * 8 + i;
            if (r < M) {
                float* cp = Cout + (size_t)r * N + col0 + tx * 8;
#pragma unroll
                for (int j = 0; j < 8; j++)
                    cp[j] = acc[i][j] + bias[col0 + tx * 8 + j];
            }
        }
    }
}

// ---------------------------------------------------------------------------
// Attention: one CTA per (b*h, j, 32-row tile). Kt/V/Qt/S fully in smem.
//   S = softmax(Q K^T * 0.125); S = w*S + (1-w)*att_map; out = S @ V
// Output written to g_att in [B][T][J][H*hd] layout (projection-ready).
// ---------------------------------------------------------------------------
#define KT_STRIDE 244
#define VS_STRIDE 68
#define S_STRIDE  245
#define ATTN_SMEM ((64*KT_STRIDE + T_*VS_STRIDE + 64*32 + 32*S_STRIDE) * 4)

__global__ __launch_bounds__(256) void attn_kernel(
    const float* __restrict__ att_map, const float* __restrict__ wptr)
{
    extern __shared__ float sm[];
    float* Kt = sm;                      // [64][244]  K transposed, col 243 zeroed
    float* Vs = Kt + 64 * KT_STRIDE;     // [243][68]
    float* Qt = Vs + T_ * VS_STRIDE;     // [64][32]   Q transposed, pad rows zero
    float* S  = Qt + 64 * 32;            // [32][245]

    int tid = threadIdx.x;
    int rt  = blockIdx.x;                // 0..7 row tile
    int j   = blockIdx.y;                // 0..16
    int bh  = blockIdx.z;                // 0..63 = b*H+h
    int r0  = rt * 32;
    int rows = min(32, T_ - r0);

    size_t base = ((size_t)bh * J_ + j) * (size_t)(T_ * HD);
    const float* qp = g_qkv + base + (size_t)r0 * HD;
    const float* kp = g_qkv + (size_t)QS + base;
    const float* vp = g_qkv + (size_t)2 * QS + base;

    float wb = wptr[0];

    for (int idx = tid; idx < T_ * HD; idx += 256) {
        int r = idx >> 6, d = idx & 63;
        Kt[d * KT_STRIDE + r] = kp[idx];
        Vs[r * VS_STRIDE + d] = vp[idx];
    }
    if (tid < 64) Kt[tid * KT_STRIDE + 243] = 0.f;
    for (int idx = tid; idx < 32 * HD; idx += 256) {
        int r = idx >> 6, d = idx & 63;
        Qt[d * 32 + r] = (r < rows) ? qp[idx] : 0.f;
    }
    __syncthreads();

    // ---- S = Q K^T * scale : 8 row-quads x 61 col-quads, 4x4 per task ----
    const float scale = 0.125f;
    for (int idx = tid; idx < 8 * 61; idx += 256) {
        int rq = idx / 61;
        int cq = idx - rq * 61;
        int r = rq << 2, c = cq << 2;
        float acc[4][4];
#pragma unroll
        for (int i = 0; i < 4; i++)
#pragma unroll
            for (int q2 = 0; q2 < 4; q2++) acc[i][q2] = 0.f;
#pragma unroll 4
        for (int d = 0; d < 64; d++) {
            float4 qv = *(const float4*)&Qt[d * 32 + r];
            float4 kv = *(const float4*)&Kt[d * KT_STRIDE + c];
            float qa[4] = {qv.x, qv.y, qv.z, qv.w};
            float ka[4] = {kv.x, kv.y, kv.z, kv.w};
#pragma unroll
            for (int i = 0; i < 4; i++)
#pragma unroll
                for (int q2 = 0; q2 < 4; q2++)
                    acc[i][q2] = fmaf(qa[i], ka[q2], acc[i][q2]);
        }
#pragma unroll
        for (int i = 0; i < 4; i++)
#pragma unroll
            for (int q2 = 0; q2 < 4; q2++)
                S[(r + i) * S_STRIDE + c + q2] = acc[i][q2] * scale;
    }
    __syncthreads();

    // ---- softmax + blend with att_map (one warp per row, 8 warps) ----
    int warp = tid >> 5, lane = tid & 31;
    float one_minus = 1.f - wb;
    for (int r = warp; r < rows; r += 8) {
        float* Sr = S + r * S_STRIDE;
        float mx = -1e30f;
        for (int c = lane; c < T_; c += 32) mx = fmaxf(mx, Sr[c]);
#pragma unroll
        for (int o = 16; o; o >>= 1) mx = fmaxf(mx, __shfl_xor_sync(0xffffffffu, mx, o));
        float sum = 0.f;
        for (int c = lane; c < T_; c += 32) {
            float e = __expf(Sr[c] - mx);
            Sr[c] = e;
            sum += e;
        }
#pragma unroll
        for (int o = 16; o; o >>= 1) sum += __shfl_xor_sync(0xffffffffu, sum, o);
        float inv = wb / sum;
        const float* am = att_map + (((size_t)bh * J_ + j) * T_ + (r0 + r)) * (size_t)T_;
        for (int c = lane; c < T_; c += 32)
            Sr[c] = Sr[c] * inv + one_minus * am[c];
    }
    __syncthreads();

    // ---- out = S @ V : 2 rows x 4 d-cols per thread (256 tasks exactly) ----
    {
        int rp = tid >> 4;              // 0..15
        int dq = (tid & 15) << 2;       // 0..60
        int r  = rp << 1;
        float acc0[4] = {0.f, 0.f, 0.f, 0.f};
        float acc1[4] = {0.f, 0.f, 0.f, 0.f};
        const float* S0 = S + r * S_STRIDE;
        const float* S1 = S0 + S_STRIDE;
        for (int c = 0; c < T_; c++) {
            float s0 = S0[c], s1 = S1[c];
            float4 vv = *(const float4*)&Vs[c * VS_STRIDE + dq];
            acc0[0] = fmaf(s0, vv.x, acc0[0]);
            acc0[1] = fmaf(s0, vv.y, acc0[1]);
            acc0[2] = fmaf(s0, vv.z, acc0[2]);
            acc0[3] = fmaf(s0, vv.w, acc0[3]);
            acc1[0] = fmaf(s1, vv.x, acc1[0]);
            acc1[1] = fmaf(s1, vv.y, acc1[1]);
            acc1[2] = fmaf(s1, vv.z, acc1[2]);
            acc1[3] = fmaf(s1, vv.w, acc1[3]);
        }
        int b = bh >> 3, h = bh & 7;
        int t0 = r0 + r;
        if (t0 < T_) {
            float* op = g_att + (((size_t)(b * T_ + t0)) * J_ + j) * C_ + h * HD + dq;
            *(float4*)op = make_float4(acc0[0], acc0[1], acc0[2], acc0[3]);
        }
        if (t0 + 1 < T_) {
            float* op = g_att + (((size_t)(b * T_ + t0 + 1)) * J_ + j) * C_ + h * HD + dq;
            *(float4*)op = make_float4(acc1[0], acc1[1], acc1[2], acc1[3]);
        }
    }
}

// ---------------------------------------------------------------------------
extern "C" void kernel_launch(void* const* d_in, const int* in_sizes, int n_in,
                              void* d_out, int out_size)
{
    const float* x      = (const float*)d_in[0];
    const float* attmap = (const float*)d_in[1];
    const float* weight = (const float*)d_in[2];
    const float* W_qkv  = (const float*)d_in[3];
    const float* W_proj = (const float*)d_in[4];
    const float* b_proj = (const float*)d_in[5];
    float* out = (float*)d_out;

    cudaFuncSetAttribute(attn_kernel,
                         cudaFuncAttributeMaxDynamicSharedMemorySize, ATTN_SMEM);

    // 1) qkv = x @ W_qkv, scattered into [3,B,H,J,T,hd]
    dim3 g1(3 * C_ / 128, (MROWS + 127) / 128);
    sgemm_kernel<<<g1, 256>>>(x, W_qkv, nullptr, nullptr, MROWS, 3 * C_, C_, 0);

    // 2) attention (softmax + att_map blend + @V), output [B,T,J,C]
    dim3 g2((T_ + 31) / 32, J_, B_ * H_);
    attn_kernel<<<g2, 256, ATTN_SMEM>>>(attmap, weight);

    // 3) out = g_att @ W_proj + b_proj
    dim3 g3(C_ / 128, (MROWS + 127) / 128);
    sgemm_kernel<<<g3, 256>>>(nullptr, W_proj, b_proj, out, MROWS, C_, C_, 1);
}

// round 2
// speedup vs baseline: 1.5149x; 1.5149x over previous
#include <cuda_runtime.h>

#define B_  8
#define T_  243
#define J_  17
#define H_  8
#define HD  64
#define C_  512
#define MROWS (B_*T_*J_)            // 33048
#define QS  (B_*H_*J_*T_*HD)        // 16920576  (== MROWS*512)

// scratch: qkv in [3][B][H][J][T][hd], attention output in [B][T][J][C]
__device__ float g_qkv[3*QS];
__device__ float g_att[QS];

__device__ __forceinline__ unsigned f2tf32(float x) {
    unsigned r;
    asm("cvt.rna.tf32.f32 %0, %1;" : "=r"(r) : "f"(x));
    return r;
}

__device__ __forceinline__ void mma_tf32(
    float& c0, float& c1, float& c2, float& c3,
    unsigned a0, unsigned a1, unsigned a2, unsigned a3,
    unsigned b0, unsigned b1)
{
    asm volatile(
        "mma.sync.aligned.m16n8k8.row.col.f32.tf32.tf32.f32 "
        "{%0,%1,%2,%3}, {%4,%5,%6,%7}, {%8,%9}, {%0,%1,%2,%3};"
        : "+f"(c0), "+f"(c1), "+f"(c2), "+f"(c3)
        : "r"(a0), "r"(a1), "r"(a2), "r"(a3), "r"(b0), "r"(b1));
}

// ---------------------------------------------------------------------------
// tf32 tensor-core GEMM, 128x128 tile, BK=16, 256 threads (8 warps, 64x32 each)
// mode 0: C = x @ W_qkv  scattered into g_qkv (q/k/v layout)
// mode 1: C = g_att @ W_proj + bias -> Cout
// ---------------------------------------------------------------------------
#define BK 16
#define SK 136   // smem row stride (words); 136%32==8 -> conflict-free frag LDS

__global__ __launch_bounds__(256, 2) void mma_gemm(
    const float* __restrict__ Ain, const float* __restrict__ Bm,
    const float* __restrict__ bias, float* __restrict__ Cout,
    int M, int N, int K, int mode)
{
    __shared__ unsigned As[BK * SK];
    __shared__ unsigned Bs[BK * SK];

    int tid  = threadIdx.x;
    int warp = tid >> 5, lane = tid & 31;
    int gid  = lane >> 2, tig = lane & 3;
    int wm   = (warp >> 2) * 64;
    int wn   = (warp & 3) * 32;
    int row0 = blockIdx.y * 128;
    int col0 = blockIdx.x * 128;

    const float* A = (mode == 1) ? g_att : Ain;

    // A tile load: 128 rows x 16 cols, thread -> (row tid/2, col (tid&1)*8), 2 float4
    int arow = tid >> 1, acol = (tid & 1) * 8;
    // B tile load: 16 rows x 128 cols, thread -> (rows (tid>>5)*2, +1, col (tid&31)*4)
    int brow = (tid >> 5) * 2, bcol = (lane) * 4;

    const float* Ag = A  + (size_t)(row0 + arow) * K + acol;
    const float* Bg = Bm + (size_t)brow * N + col0 + bcol;
    bool aok = (row0 + arow) < M;

    float c[4][4][4];
#pragma unroll
    for (int mt = 0; mt < 4; mt++)
#pragma unroll
        for (int nt = 0; nt < 4; nt++)
#pragma unroll
            for (int i = 0; i < 4; i++) c[mt][nt][i] = 0.f;

    float4 pa0, pa1, pb0, pb1;
    pa0 = aok ? *(const float4*)Ag       : make_float4(0,0,0,0);
    pa1 = aok ? *(const float4*)(Ag + 4) : make_float4(0,0,0,0);
    pb0 = *(const float4*)Bg;
    pb1 = *(const float4*)(Bg + N);

    for (int k0 = 0; k0 < K; k0 += BK) {
        // store staged tile (convert to tf32)
        As[(acol + 0) * SK + arow] = f2tf32(pa0.x);
        As[(acol + 1) * SK + arow] = f2tf32(pa0.y);
        As[(acol + 2) * SK + arow] = f2tf32(pa0.z);
        As[(acol + 3) * SK + arow] = f2tf32(pa0.w);
        As[(acol + 4) * SK + arow] = f2tf32(pa1.x);
        As[(acol + 5) * SK + arow] = f2tf32(pa1.y);
        As[(acol + 6) * SK + arow] = f2tf32(pa1.z);
        As[(acol + 7) * SK + arow] = f2tf32(pa1.w);
        {
            uint4 u0 = make_uint4(f2tf32(pb0.x), f2tf32(pb0.y), f2tf32(pb0.z), f2tf32(pb0.w));
            uint4 u1 = make_uint4(f2tf32(pb1.x), f2tf32(pb1.y), f2tf32(pb1.z), f2tf32(pb1.w));
            *(uint4*)&Bs[(brow + 0) * SK + bcol] = u0;
            *(uint4*)&Bs[(brow + 1) * SK + bcol] = u1;
        }
        __syncthreads();

        // prefetch next tile into registers
        if (k0 + BK < K) {
            Ag += BK;
            Bg += (size_t)BK * N;
            pa0 = aok ? *(const float4*)Ag       : make_float4(0,0,0,0);
            pa1 = aok ? *(const float4*)(Ag + 4) : make_float4(0,0,0,0);
            pb0 = *(const float4*)Bg;
            pb1 = *(const float4*)(Bg + N);
        }

#pragma unroll
        for (int ks = 0; ks < BK; ks += 8) {
            unsigned af[4][4], bf[4][2];
#pragma unroll
            for (int mt = 0; mt < 4; mt++) {
                int m = wm + mt * 16 + gid;
                af[mt][0] = As[(ks + tig)     * SK + m];
                af[mt][1] = As[(ks + tig)     * SK + m + 8];
                af[mt][2] = As[(ks + tig + 4) * SK + m];
                af[mt][3] = As[(ks + tig + 4) * SK + m + 8];
            }
#pragma unroll
            for (int nt = 0; nt < 4; nt++) {
                int n = wn + nt * 8 + gid;
                bf[nt][0] = Bs[(ks + tig)     * SK + n];
                bf[nt][1] = Bs[(ks + tig + 4) * SK + n];
            }
#pragma unroll
            for (int mt = 0; mt < 4; mt++)
#pragma unroll
                for (int nt = 0; nt < 4; nt++)
                    mma_tf32(c[mt][nt][0], c[mt][nt][1], c[mt][nt][2], c[mt][nt][3],
                             af[mt][0], af[mt][1], af[mt][2], af[mt][3],
                             bf[nt][0], bf[nt][1]);
        }
        __syncthreads();
    }

    // ---- epilogue ----
    if (mode == 0) {
        // scatter into g_qkv[which][b][h][j][t][d]
#pragma unroll
        for (int mt = 0; mt < 4; mt++) {
            int r1 = row0 + wm + mt * 16 + gid;
            int r2 = r1 + 8;
#pragma unroll
            for (int half = 0; half < 2; half++) {
                int r = half ? r2 : r1;
                if (r < MROWS) {
                    int b   = r / (T_ * J_);
                    int rem = r - b * (T_ * J_);
                    int t   = rem / J_;
                    int jj  = rem - t * J_;
                    size_t rowbase = (((size_t)b * H_) * J_ + jj) * T_ + t;
#pragma unroll
                    for (int nt = 0; nt < 4; nt++) {
                        int cb = col0 + wn + nt * 8 + 2 * tig;
                        int which = cb >> 9;
                        int h = (cb >> 6) & 7;
                        int d = cb & 63;
                        size_t dst = (size_t)which * QS +
                            ((((size_t)(b * H_ + h) * J_ + jj) * T_ + t) * HD + d);
                        float2 v = half ? make_float2(c[mt][nt][2], c[mt][nt][3])
                                        : make_float2(c[mt][nt][0], c[mt][nt][1]);
                        *(float2*)&g_qkv[dst] = v;
                    }
                    (void)rowbase;
                }
            }
        }
    } else {
#pragma unroll
        for (int mt = 0; mt < 4; mt++) {
            int r1 = row0 + wm + mt * 16 + gid;
            int r2 = r1 + 8;
#pragma unroll
            for (int nt = 0; nt < 4; nt++) {
                int cb = col0 + wn + nt * 8 + 2 * tig;
                float2 bb = *(const float2*)&bias[cb];
                if (r1 < MROWS) {
                    float2 v = make_float2(c[mt][nt][0] + bb.x, c[mt][nt][1] + bb.y);
                    *(float2*)&Cout[(size_t)r1 * N + cb] = v;
                }
                if (r2 < MROWS) {
                    float2 v = make_float2(c[mt][nt][2] + bb.x, c[mt][nt][3] + bb.y);
                    *(float2*)&Cout[(size_t)r2 * N + cb] = v;
                }
            }
        }
    }
}

// ---------------------------------------------------------------------------
// Attention: one CTA per (b*h, j, 32-row tile). Kt/V/Qt/S fully in smem.
//   S = softmax(Q K^T * 0.125); S = w*S + (1-w)*att_map; out = S @ V
// Output written to g_att in [B][T][J][H*hd] layout (projection-ready).
// ---------------------------------------------------------------------------
#define KT_STRIDE 244
#define VS_STRIDE 68
#define S_STRIDE  245
#define ATTN_SMEM ((64*KT_STRIDE + T_*VS_STRIDE + 64*32 + 32*S_STRIDE) * 4)

__global__ __launch_bounds__(256) void attn_kernel(
    const float* __restrict__ att_map, const float* __restrict__ wptr)
{
    extern __shared__ float sm[];
    float* Kt = sm;                      // [64][244]  K transposed, col 243 zeroed
    float* Vs = Kt + 64 * KT_STRIDE;     // [243][68]
    float* Qt = Vs + T_ * VS_STRIDE;     // [64][32]   Q transposed, pad rows zero
    float* S  = Qt + 64 * 32;            // [32][245]

    int tid = threadIdx.x;
    int rt  = blockIdx.x;                // 0..7 row tile
    int j   = blockIdx.y;                // 0..16
    int bh  = blockIdx.z;                // 0..63 = b*H+h
    int r0  = rt * 32;
    int rows = min(32, T_ - r0);

    size_t base = ((size_t)bh * J_ + j) * (size_t)(T_ * HD);
    const float* qp = g_qkv + base + (size_t)r0 * HD;
    const float* kp = g_qkv + (size_t)QS + base;
    const float* vp = g_qkv + (size_t)2 * QS + base;

    float wb = wptr[0];

    for (int idx = tid; idx < T_ * HD; idx += 256) {
        int r = idx >> 6, d = idx & 63;
        Kt[d * KT_STRIDE + r] = kp[idx];
        Vs[r * VS_STRIDE + d] = vp[idx];
    }
    if (tid < 64) Kt[tid * KT_STRIDE + 243] = 0.f;
    for (int idx = tid; idx < 32 * HD; idx += 256) {
        int r = idx >> 6, d = idx & 63;
        Qt[d * 32 + r] = (r < rows) ? qp[idx] : 0.f;
    }
    __syncthreads();

    // ---- S = Q K^T * scale : 8 row-quads x 61 col-quads, 4x4 per task ----
    const float scale = 0.125f;
    for (int idx = tid; idx < 8 * 61; idx += 256) {
        int rq = idx / 61;
        int cq = idx - rq * 61;
        int r = rq << 2, c = cq << 2;
        float acc[4][4];
#pragma unroll
        for (int i = 0; i < 4; i++)
#pragma unroll
            for (int q2 = 0; q2 < 4; q2++) acc[i][q2] = 0.f;
#pragma unroll 4
        for (int d = 0; d < 64; d++) {
            float4 qv = *(const float4*)&Qt[d * 32 + r];
            float4 kv = *(const float4*)&Kt[d * KT_STRIDE + c];
            float qa[4] = {qv.x, qv.y, qv.z, qv.w};
            float ka[4] = {kv.x, kv.y, kv.z, kv.w};
#pragma unroll
            for (int i = 0; i < 4; i++)
#pragma unroll
                for (int q2 = 0; q2 < 4; q2++)
                    acc[i][q2] = fmaf(qa[i], ka[q2], acc[i][q2]);
        }
#pragma unroll
        for (int i = 0; i < 4; i++)
#pragma unroll
            for (int q2 = 0; q2 < 4; q2++)
                S[(r + i) * S_STRIDE + c + q2] = acc[i][q2] * scale;
    }
    __syncthreads();

    // ---- softmax + blend with att_map (one warp per row, 8 warps) ----
    int warp = tid >> 5, lane = tid & 31;
    float one_minus = 1.f - wb;
    for (int r = warp; r < rows; r += 8) {
        float* Sr = S + r * S_STRIDE;
        float mx = -1e30f;
        for (int c = lane; c < T_; c += 32) mx = fmaxf(mx, Sr[c]);
#pragma unroll
        for (int o = 16; o; o >>= 1) mx = fmaxf(mx, __shfl_xor_sync(0xffffffffu, mx, o));
        float sum = 0.f;
        for (int c = lane; c < T_; c += 32) {
            float e = __expf(Sr[c] - mx);
            Sr[c] = e;
            sum += e;
        }
#pragma unroll
        for (int o = 16; o; o >>= 1) sum += __shfl_xor_sync(0xffffffffu, sum, o);
        float inv = wb / sum;
        const float* am = att_map + (((size_t)bh * J_ + j) * T_ + (r0 + r)) * (size_t)T_;
        for (int c = lane; c < T_; c += 32)
            Sr[c] = Sr[c] * inv + one_minus * am[c];
    }
    __syncthreads();

    // ---- out = S @ V : 2 rows x 4 d-cols per thread (256 tasks exactly) ----
    {
        int rp = tid >> 4;              // 0..15
        int dq = (tid & 15) << 2;       // 0..60
        int r  = rp << 1;
        float acc0[4] = {0.f, 0.f, 0.f, 0.f};
        float acc1[4] = {0.f, 0.f, 0.f, 0.f};
        const float* S0 = S + r * S_STRIDE;
        const float* S1 = S0 + S_STRIDE;
        for (int c = 0; c < T_; c++) {
            float s0 = S0[c], s1 = S1[c];
            float4 vv = *(const float4*)&Vs[c * VS_STRIDE + dq];
            acc0[0] = fmaf(s0, vv.x, acc0[0]);
            acc0[1] = fmaf(s0, vv.y, acc0[1]);
            acc0[2] = fmaf(s0, vv.z, acc0[2]);
            acc0[3] = fmaf(s0, vv.w, acc0[3]);
            acc1[0] = fmaf(s1, vv.x, acc1[0]);
            acc1[1] = fmaf(s1, vv.y, acc1[1]);
            acc1[2] = fmaf(s1, vv.z, acc1[2]);
            acc1[3] = fmaf(s1, vv.w, acc1[3]);
        }
        int b = bh >> 3, h = bh & 7;
        int t0 = r0 + r;
        if (t0 < T_) {
            float* op = g_att + (((size_t)(b * T_ + t0)) * J_ + j) * C_ + h * HD + dq;
            *(float4*)op = make_float4(acc0[0], acc0[1], acc0[2], acc0[3]);
        }
        if (t0 + 1 < T_) {
            float* op = g_att + (((size_t)(b * T_ + t0 + 1)) * J_ + j) * C_ + h * HD + dq;
            *(float4*)op = make_float4(acc1[0], acc1[1], acc1[2], acc1[3]);
        }
    }
}

// ---------------------------------------------------------------------------
extern "C" void kernel_launch(void* const* d_in, const int* in_sizes, int n_in,
                              void* d_out, int out_size)
{
    const float* x      = (const float*)d_in[0];
    const float* attmap = (const float*)d_in[1];
    const float* weight = (const float*)d_in[2];
    const float* W_qkv  = (const float*)d_in[3];
    const float* W_proj = (const float*)d_in[4];
    const float* b_proj = (const float*)d_in[5];
    float* out = (float*)d_out;

    cudaFuncSetAttribute(attn_kernel,
                         cudaFuncAttributeMaxDynamicSharedMemorySize, ATTN_SMEM);

    // 1) qkv = x @ W_qkv, scattered into [3,B,H,J,T,hd]
    dim3 g1(3 * C_ / 128, (MROWS + 127) / 128);
    mma_gemm<<<g1, 256>>>(x, W_qkv, nullptr, nullptr, MROWS, 3 * C_, C_, 0);

    // 2) attention (softmax + att_map blend + @V), output [B,T,J,C]
    dim3 g2((T_ + 31) / 32, J_, B_ * H_);
    attn_kernel<<<g2, 256, ATTN_SMEM>>>(attmap, weight);

    // 3) out = g_att @ W_proj + b_proj
    dim3 g3(C_ / 128, (MROWS + 127) / 128);
    mma_gemm<<<g3, 256>>>(nullptr, W_proj, b_proj, out, MROWS, C_, C_, 1);
}

// round 3
// speedup vs baseline: 2.1059x; 1.3902x over previous
#include <cuda_runtime.h>

#define B_  8
#define T_  243
#define J_  17
#define H_  8
#define HD  64
#define C_  512
#define MROWS (B_*T_*J_)            // 33048
#define QS  (B_*H_*J_*T_*HD)        // 16920576

__device__ float g_qkv[3*QS];
__device__ float g_att[QS];

__device__ __forceinline__ unsigned f2tf32(float x) {
    unsigned r;
    asm("cvt.rna.tf32.f32 %0, %1;" : "=r"(r) : "f"(x));
    return r;
}

__device__ __forceinline__ void mma_tf32(
    float& c0, float& c1, float& c2, float& c3,
    unsigned a0, unsigned a1, unsigned a2, unsigned a3,
    unsigned b0, unsigned b1)
{
    asm volatile(
        "mma.sync.aligned.m16n8k8.row.col.f32.tf32.tf32.f32 "
        "{%0,%1,%2,%3}, {%4,%5,%6,%7}, {%8,%9}, {%0,%1,%2,%3};"
        : "+f"(c0), "+f"(c1), "+f"(c2), "+f"(c3)
        : "r"(a0), "r"(a1), "r"(a2), "r"(a3), "r"(b0), "r"(b1));
}

// ---------------------------------------------------------------------------
// tf32 tensor-core GEMM, 128x128 tile, BK=16, 256 threads (8 warps, 64x32 each)
// ---------------------------------------------------------------------------
#define BK 16
#define SK 136

__global__ __launch_bounds__(256, 2) void mma_gemm(
    const float* __restrict__ Ain, const float* __restrict__ Bm,
    const float* __restrict__ bias, float* __restrict__ Cout,
    int M, int N, int K, int mode)
{
    __shared__ unsigned As[BK * SK];
    __shared__ unsigned Bs[BK * SK];

    int tid  = threadIdx.x;
    int warp = tid >> 5, lane = tid & 31;
    int gid  = lane >> 2, tig = lane & 3;
    int wm   = (warp >> 2) * 64;
    int wn   = (warp & 3) * 32;
    int row0 = blockIdx.y * 128;
    int col0 = blockIdx.x * 128;

    const float* A = (mode == 1) ? g_att : Ain;

    int arow = tid >> 1, acol = (tid & 1) * 8;
    int brow = (tid >> 5) * 2, bcol = lane * 4;

    const float* Ag = A  + (size_t)(row0 + arow) * K + acol;
    const float* Bg = Bm + (size_t)brow * N + col0 + bcol;
    bool aok = (row0 + arow) < M;

    float c[4][4][4];
#pragma unroll
    for (int mt = 0; mt < 4; mt++)
#pragma unroll
        for (int nt = 0; nt < 4; nt++)
#pragma unroll
            for (int i = 0; i < 4; i++) c[mt][nt][i] = 0.f;

    float4 pa0, pa1, pb0, pb1;
    pa0 = aok ? *(const float4*)Ag       : make_float4(0,0,0,0);
    pa1 = aok ? *(const float4*)(Ag + 4) : make_float4(0,0,0,0);
    pb0 = *(const float4*)Bg;
    pb1 = *(const float4*)(Bg + N);

    for (int k0 = 0; k0 < K; k0 += BK) {
        As[(acol + 0) * SK + arow] = f2tf32(pa0.x);
        As[(acol + 1) * SK + arow] = f2tf32(pa0.y);
        As[(acol + 2) * SK + arow] = f2tf32(pa0.z);
        As[(acol + 3) * SK + arow] = f2tf32(pa0.w);
        As[(acol + 4) * SK + arow] = f2tf32(pa1.x);
        As[(acol + 5) * SK + arow] = f2tf32(pa1.y);
        As[(acol + 6) * SK + arow] = f2tf32(pa1.z);
        As[(acol + 7) * SK + arow] = f2tf32(pa1.w);
        {
            uint4 u0 = make_uint4(f2tf32(pb0.x), f2tf32(pb0.y), f2tf32(pb0.z), f2tf32(pb0.w));
            uint4 u1 = make_uint4(f2tf32(pb1.x), f2tf32(pb1.y), f2tf32(pb1.z), f2tf32(pb1.w));
            *(uint4*)&Bs[(brow + 0) * SK + bcol] = u0;
            *(uint4*)&Bs[(brow + 1) * SK + bcol] = u1;
        }
        __syncthreads();

        if (k0 + BK < K) {
            Ag += BK;
            Bg += (size_t)BK * N;
            pa0 = aok ? *(const float4*)Ag       : make_float4(0,0,0,0);
            pa1 = aok ? *(const float4*)(Ag + 4) : make_float4(0,0,0,0);
            pb0 = *(const float4*)Bg;
            pb1 = *(const float4*)(Bg + N);
        }

#pragma unroll
        for (int ks = 0; ks < BK; ks += 8) {
            unsigned af[4][4], bf[4][2];
#pragma unroll
            for (int mt = 0; mt < 4; mt++) {
                int m = wm + mt * 16 + gid;
                af[mt][0] = As[(ks + tig)     * SK + m];
                af[mt][1] = As[(ks + tig)     * SK + m + 8];
                af[mt][2] = As[(ks + tig + 4) * SK + m];
                af[mt][3] = As[(ks + tig + 4) * SK + m + 8];
            }
#pragma unroll
            for (int nt = 0; nt < 4; nt++) {
                int n = wn + nt * 8 + gid;
                bf[nt][0] = Bs[(ks + tig)     * SK + n];
                bf[nt][1] = Bs[(ks + tig + 4) * SK + n];
            }
#pragma unroll
            for (int mt = 0; mt < 4; mt++)
#pragma unroll
                for (int nt = 0; nt < 4; nt++)
                    mma_tf32(c[mt][nt][0], c[mt][nt][1], c[mt][nt][2], c[mt][nt][3],
                             af[mt][0], af[mt][1], af[mt][2], af[mt][3],
                             bf[nt][0], bf[nt][1]);
        }
        __syncthreads();
    }

    if (mode == 0) {
#pragma unroll
        for (int mt = 0; mt < 4; mt++) {
            int r1 = row0 + wm + mt * 16 + gid;
#pragma unroll
            for (int half = 0; half < 2; half++) {
                int r = half ? (r1 + 8) : r1;
                if (r < MROWS) {
                    int b   = r / (T_ * J_);
                    int rem = r - b * (T_ * J_);
                    int t   = rem / J_;
                    int jj  = rem - t * J_;
#pragma unroll
                    for (int nt = 0; nt < 4; nt++) {
                        int cb = col0 + wn + nt * 8 + 2 * tig;
                        int which = cb >> 9;
                        int h = (cb >> 6) & 7;
                        int d = cb & 63;
                        size_t dst = (size_t)which * QS +
                            ((((size_t)(b * H_ + h) * J_ + jj) * T_ + t) * HD + d);
                        float2 v = half ? make_float2(c[mt][nt][2], c[mt][nt][3])
                                        : make_float2(c[mt][nt][0], c[mt][nt][1]);
                        *(float2*)&g_qkv[dst] = v;
                    }
                }
            }
        }
    } else {
#pragma unroll
        for (int mt = 0; mt < 4; mt++) {
            int r1 = row0 + wm + mt * 16 + gid;
            int r2 = r1 + 8;
#pragma unroll
            for (int nt = 0; nt < 4; nt++) {
                int cb = col0 + wn + nt * 8 + 2 * tig;
                float2 bb = *(const float2*)&bias[cb];
                if (r1 < MROWS)
                    *(float2*)&Cout[(size_t)r1 * N + cb] =
                        make_float2(c[mt][nt][0] + bb.x, c[mt][nt][1] + bb.y);
                if (r2 < MROWS)
                    *(float2*)&Cout[(size_t)r2 * N + cb] =
                        make_float2(c[mt][nt][2] + bb.x, c[mt][nt][3] + bb.y);
            }
        }
    }
}

// ---------------------------------------------------------------------------
// tf32 MMA attention. One CTA per (bh, j, 64-row tile). 8 warps.
// smem: Qt[d=64][t=72pad], Ks[s=256][d=68pad], Vt[d=64][s=260pad], S[t=64][s=260pad]
// s padded to 256 with zeroed K/V rows -> pad score cols are exact 0.
// ---------------------------------------------------------------------------
#define ANP 256       // padded s
#define QSTR 72
#define KSTR 68
#define VSTR 260
#define SSTR 260
#define ATTN_SMEM ((64*QSTR + ANP*KSTR + 64*VSTR + 64*SSTR) * 4)  // 221184 B

__global__ __launch_bounds__(256, 1) void attn_kernel(
    const float* __restrict__ att_map, const float* __restrict__ wptr)
{
    extern __shared__ float sm[];
    unsigned* Qt = (unsigned*)sm;                 // [64][QSTR]
    unsigned* Ks = Qt + 64 * QSTR;                // [256][KSTR]
    unsigned* Vt = Ks + ANP * KSTR;               // [64][VSTR]
    float*    S  = (float*)(Vt + 64 * VSTR);      // [64][SSTR]

    int tid  = threadIdx.x;
    int warp = tid >> 5, lane = tid & 31;
    int gid  = lane >> 2, tig = lane & 3;

    int rt = blockIdx.x;                 // 0..3 row tile (64 rows)
    int j  = blockIdx.y;
    int bh = blockIdx.z;
    int r0 = rt * 64;
    int rows = min(64, T_ - r0);

    size_t base = ((size_t)bh * J_ + j) * (size_t)(T_ * HD);
    const float* qp = g_qkv + base + (size_t)r0 * HD;
    const float* kp = g_qkv + (size_t)QS + base;
    const float* vp = g_qkv + (size_t)2 * QS + base;
    float wb = wptr[0];

    // loads (transpose into padded smem, convert to tf32)
    for (int idx = tid; idx < ANP * HD; idx += 256) {
        int s = idx >> 6, d = idx & 63;
        float kv = (s < T_) ? kp[idx] : 0.f;
        float vv = (s < T_) ? vp[idx] : 0.f;
        Ks[s * KSTR + d] = f2tf32(kv);
        Vt[d * VSTR + s] = f2tf32(vv);
    }
    for (int idx = tid; idx < 64 * HD; idx += 256) {
        int t = idx >> 6, d = idx & 63;
        float qv = (t < rows) ? qp[idx] : 0.f;
        Qt[d * QSTR + t] = f2tf32(qv);
    }
    __syncthreads();

    // ---- S = Q K^T * 0.125 via MMA.  warps: 2 in m (32), 4 in n (64) ----
    {
        int wm = (warp & 1) * 32;
        int wn = (warp >> 1) * 64;
        float c[2][8][4];
#pragma unroll
        for (int mt = 0; mt < 2; mt++)
#pragma unroll
            for (int nt = 0; nt < 8; nt++)
#pragma unroll
                for (int i = 0; i < 4; i++) c[mt][nt][i] = 0.f;

#pragma unroll
        for (int k0 = 0; k0 < HD; k0 += 8) {
            unsigned a[2][4];
#pragma unroll
            for (int mt = 0; mt < 2; mt++) {
                int m = wm + mt * 16 + gid;
                a[mt][0] = Qt[(k0 + tig)     * QSTR + m];
                a[mt][1] = Qt[(k0 + tig)     * QSTR + m + 8];
                a[mt][2] = Qt[(k0 + tig + 4) * QSTR + m];
                a[mt][3] = Qt[(k0 + tig + 4) * QSTR + m + 8];
            }
#pragma unroll
            for (int nt = 0; nt < 8; nt++) {
                int n = wn + nt * 8 + gid;
                unsigned b0 = Ks[n * KSTR + k0 + tig];
                unsigned b1 = Ks[n * KSTR + k0 + tig + 4];
#pragma unroll
                for (int mt = 0; mt < 2; mt++)
                    mma_tf32(c[mt][nt][0], c[mt][nt][1], c[mt][nt][2], c[mt][nt][3],
                             a[mt][0], a[mt][1], a[mt][2], a[mt][3], b0, b1);
            }
        }
        const float scale = 0.125f;
#pragma unroll
        for (int mt = 0; mt < 2; mt++) {
            int m = wm + mt * 16 + gid;
#pragma unroll
            for (int nt = 0; nt < 8; nt++) {
                int n = wn + nt * 8 + 2 * tig;
                *(float2*)&S[m * SSTR + n] =
                    make_float2(c[mt][nt][0] * scale, c[mt][nt][1] * scale);
                *(float2*)&S[(m + 8) * SSTR + n] =
                    make_float2(c[mt][nt][2] * scale, c[mt][nt][3] * scale);
            }
        }
    }
    __syncthreads();

    // ---- softmax + blend (warp per row). pad cols stay exact 0. ----
    float one_minus = 1.f - wb;
    for (int r = warp; r < rows; r += 8) {
        float* Sr = S + r * SSTR;
        float mx = -1e30f;
        for (int c = lane; c < T_; c += 32) mx = fmaxf(mx, Sr[c]);
#pragma unroll
        for (int o = 16; o; o >>= 1) mx = fmaxf(mx, __shfl_xor_sync(0xffffffffu, mx, o));
        float sum = 0.f;
        for (int c = lane; c < T_; c += 32) {
            float e = __expf(Sr[c] - mx);
            Sr[c] = e;
            sum += e;
        }
#pragma unroll
        for (int o = 16; o; o >>= 1) sum += __shfl_xor_sync(0xffffffffu, sum, o);
        float inv = wb / sum;
        const float* am = att_map + (((size_t)bh * J_ + j) * T_ + (r0 + r)) * (size_t)T_;
        for (int c = lane; c < T_; c += 32)
            Sr[c] = Sr[c] * inv + one_minus * am[c];
    }
    __syncthreads();

    // ---- out = S @ V via MMA.  warps: 4 in m (16 each), 2 in n (32 each) ----
    {
        int wm = (warp & 3) * 16;
        int wn = (warp >> 2) * 32;
        float c[4][4];
#pragma unroll
        for (int nt = 0; nt < 4; nt++)
#pragma unroll
            for (int i = 0; i < 4; i++) c[nt][i] = 0.f;

#pragma unroll 4
        for (int k0 = 0; k0 < ANP; k0 += 8) {
            int m = wm + gid;
            unsigned a0 = f2tf32(S[m * SSTR + k0 + tig]);
            unsigned a1 = f2tf32(S[(m + 8) * SSTR + k0 + tig]);
            unsigned a2 = f2tf32(S[m * SSTR + k0 + tig + 4]);
            unsigned a3 = f2tf32(S[(m + 8) * SSTR + k0 + tig + 4]);
#pragma unroll
            for (int nt = 0; nt < 4; nt++) {
                int n = wn + nt * 8 + gid;
                unsigned b0 = Vt[n * VSTR + k0 + tig];
                unsigned b1 = Vt[n * VSTR + k0 + tig + 4];
                mma_tf32(c[nt][0], c[nt][1], c[nt][2], c[nt][3],
                         a0, a1, a2, a3, b0, b1);
            }
        }

        int b = bh >> 3, h = bh & 7;
        int t1 = r0 + wm + gid;
        int t2 = t1 + 8;
#pragma unroll
        for (int nt = 0; nt < 4; nt++) {
            int col = h * HD + wn + nt * 8 + 2 * tig;
            if (t1 < T_) {
                float* op = g_att + (((size_t)(b * T_ + t1)) * J_ + j) * C_ + col;
                *(float2*)op = make_float2(c[nt][0], c[nt][1]);
            }
            if (t2 < T_) {
                float* op = g_att + (((size_t)(b * T_ + t2)) * J_ + j) * C_ + col;
                *(float2*)op = make_float2(c[nt][2], c[nt][3]);
            }
        }
    }
}

// ---------------------------------------------------------------------------
extern "C" void kernel_launch(void* const* d_in, const int* in_sizes, int n_in,
                              void* d_out, int out_size)
{
    const float* x      = (const float*)d_in[0];
    const float* attmap = (const float*)d_in[1];
    const float* weight = (const float*)d_in[2];
    const float* W_qkv  = (const float*)d_in[3];
    const float* W_proj = (const float*)d_in[4];
    const float* b_proj = (const float*)d_in[5];
    float* out = (float*)d_out;

    cudaFuncSetAttribute(attn_kernel,
                         cudaFuncAttributeMaxDynamicSharedMemorySize, ATTN_SMEM);

    dim3 g1(3 * C_ / 128, (MROWS + 127) / 128);
    mma_gemm<<<g1, 256>>>(x, W_qkv, nullptr, nullptr, MROWS, 3 * C_, C_, 0);

    dim3 g2((T_ + 63) / 64, J_, B_ * H_);
    attn_kernel<<<g2, 256, ATTN_SMEM>>>(attmap, weight);

    dim3 g3(C_ / 128, (MROWS + 127) / 128);
    mma_gemm<<<g3, 256>>>(nullptr, W_proj, b_proj, out, MROWS, C_, C_, 1);
}

// round 4
// speedup vs baseline: 3.1142x; 1.4788x over previous
#include <cuda_runtime.h>

#define B_  8
#define T_  243
#define J_  17
#define H_  8
#define HD  64
#define C_  512
#define MROWS (B_*T_*J_)            // 33048
#define QS  (B_*H_*J_*T_*HD)        // 16920576

__device__ float g_qkv[3*QS];
__device__ float g_att[QS];

__device__ __forceinline__ unsigned f2tf32(float x) {
    unsigned r;
    asm("cvt.rna.tf32.f32 %0, %1;" : "=r"(r) : "f"(x));
    return r;
}

__device__ __forceinline__ void mma_tf32(
    float& c0, float& c1, float& c2, float& c3,
    unsigned a0, unsigned a1, unsigned a2, unsigned a3,
    unsigned b0, unsigned b1)
{
    asm volatile(
        "mma.sync.aligned.m16n8k8.row.col.f32.tf32.tf32.f32 "
        "{%0,%1,%2,%3}, {%4,%5,%6,%7}, {%8,%9}, {%0,%1,%2,%3};"
        : "+f"(c0), "+f"(c1), "+f"(c2), "+f"(c3)
        : "r"(a0), "r"(a1), "r"(a2), "r"(a3), "r"(b0), "r"(b1));
}

// ---------------------------------------------------------------------------
// tf32 tensor-core GEMM, 128x128 tile, BK=16, 256 threads (8 warps, 64x32 each)
// ---------------------------------------------------------------------------
#define BK 16
#define SK 136

__global__ __launch_bounds__(256, 2) void mma_gemm(
    const float* __restrict__ Ain, const float* __restrict__ Bm,
    const float* __restrict__ bias, float* __restrict__ Cout,
    int M, int N, int K, int mode)
{
    __shared__ unsigned As[BK * SK];
    __shared__ unsigned Bs[BK * SK];

    int tid  = threadIdx.x;
    int warp = tid >> 5, lane = tid & 31;
    int gid  = lane >> 2, tig = lane & 3;
    int wm   = (warp >> 2) * 64;
    int wn   = (warp & 3) * 32;
    int row0 = blockIdx.y * 128;
    int col0 = blockIdx.x * 128;

    const float* A = (mode == 1) ? g_att : Ain;

    int arow = tid >> 1, acol = (tid & 1) * 8;
    int brow = (tid >> 5) * 2, bcol = lane * 4;

    const float* Ag = A  + (size_t)(row0 + arow) * K + acol;
    const float* Bg = Bm + (size_t)brow * N + col0 + bcol;
    bool aok = (row0 + arow) < M;

    float c[4][4][4];
#pragma unroll
    for (int mt = 0; mt < 4; mt++)
#pragma unroll
        for (int nt = 0; nt < 4; nt++)
#pragma unroll
            for (int i = 0; i < 4; i++) c[mt][nt][i] = 0.f;

    float4 pa0, pa1, pb0, pb1;
    pa0 = aok ? *(const float4*)Ag       : make_float4(0,0,0,0);
    pa1 = aok ? *(const float4*)(Ag + 4) : make_float4(0,0,0,0);
    pb0 = *(const float4*)Bg;
    pb1 = *(const float4*)(Bg + N);

    for (int k0 = 0; k0 < K; k0 += BK) {
        As[(acol + 0) * SK + arow] = f2tf32(pa0.x);
        As[(acol + 1) * SK + arow] = f2tf32(pa0.y);
        As[(acol + 2) * SK + arow] = f2tf32(pa0.z);
        As[(acol + 3) * SK + arow] = f2tf32(pa0.w);
        As[(acol + 4) * SK + arow] = f2tf32(pa1.x);
        As[(acol + 5) * SK + arow] = f2tf32(pa1.y);
        As[(acol + 6) * SK + arow] = f2tf32(pa1.z);
        As[(acol + 7) * SK + arow] = f2tf32(pa1.w);
        {
            uint4 u0 = make_uint4(f2tf32(pb0.x), f2tf32(pb0.y), f2tf32(pb0.z), f2tf32(pb0.w));
            uint4 u1 = make_uint4(f2tf32(pb1.x), f2tf32(pb1.y), f2tf32(pb1.z), f2tf32(pb1.w));
            *(uint4*)&Bs[(brow + 0) * SK + bcol] = u0;
            *(uint4*)&Bs[(brow + 1) * SK + bcol] = u1;
        }
        __syncthreads();

        if (k0 + BK < K) {
            Ag += BK;
            Bg += (size_t)BK * N;
            pa0 = aok ? *(const float4*)Ag       : make_float4(0,0,0,0);
            pa1 = aok ? *(const float4*)(Ag + 4) : make_float4(0,0,0,0);
            pb0 = *(const float4*)Bg;
            pb1 = *(const float4*)(Bg + N);
        }

#pragma unroll
        for (int ks = 0; ks < BK; ks += 8) {
            unsigned af[4][4], bf[4][2];
#pragma unroll
            for (int mt = 0; mt < 4; mt++) {
                int m = wm + mt * 16 + gid;
                af[mt][0] = As[(ks + tig)     * SK + m];
                af[mt][1] = As[(ks + tig)     * SK + m + 8];
                af[mt][2] = As[(ks + tig + 4) * SK + m];
                af[mt][3] = As[(ks + tig + 4) * SK + m + 8];
            }
#pragma unroll
            for (int nt = 0; nt < 4; nt++) {
                int n = wn + nt * 8 + gid;
                bf[nt][0] = Bs[(ks + tig)     * SK + n];
                bf[nt][1] = Bs[(ks + tig + 4) * SK + n];
            }
#pragma unroll
            for (int mt = 0; mt < 4; mt++)
#pragma unroll
                for (int nt = 0; nt < 4; nt++)
                    mma_tf32(c[mt][nt][0], c[mt][nt][1], c[mt][nt][2], c[mt][nt][3],
                             af[mt][0], af[mt][1], af[mt][2], af[mt][3],
                             bf[nt][0], bf[nt][1]);
        }
        __syncthreads();
    }

    if (mode == 0) {
#pragma unroll
        for (int mt = 0; mt < 4; mt++) {
            int r1 = row0 + wm + mt * 16 + gid;
#pragma unroll
            for (int half = 0; half < 2; half++) {
                int r = half ? (r1 + 8) : r1;
                if (r < MROWS) {
                    int b   = r / (T_ * J_);
                    int rem = r - b * (T_ * J_);
                    int t   = rem / J_;
                    int jj  = rem - t * J_;
#pragma unroll
                    for (int nt = 0; nt < 4; nt++) {
                        int cb = col0 + wn + nt * 8 + 2 * tig;
                        int which = cb >> 9;
                        int h = (cb >> 6) & 7;
                        int d = cb & 63;
                        size_t dst = (size_t)which * QS +
                            ((((size_t)(b * H_ + h) * J_ + jj) * T_ + t) * HD + d);
                        float2 v = half ? make_float2(c[mt][nt][2], c[mt][nt][3])
                                        : make_float2(c[mt][nt][0], c[mt][nt][1]);
                        *(float2*)&g_qkv[dst] = v;
                    }
                }
            }
        }
    } else {
#pragma unroll
        for (int mt = 0; mt < 4; mt++) {
            int r1 = row0 + wm + mt * 16 + gid;
            int r2 = r1 + 8;
#pragma unroll
            for (int nt = 0; nt < 4; nt++) {
                int cb = col0 + wn + nt * 8 + 2 * tig;
                float2 bb = *(const float2*)&bias[cb];
                if (r1 < MROWS)
                    *(float2*)&Cout[(size_t)r1 * N + cb] =
                        make_float2(c[mt][nt][0] + bb.x, c[mt][nt][1] + bb.y);
                if (r2 < MROWS)
                    *(float2*)&Cout[(size_t)r2 * N + cb] =
                        make_float2(c[mt][nt][2] + bb.x, c[mt][nt][3] + bb.y);
            }
        }
    }
}

// ---------------------------------------------------------------------------
// tf32 MMA attention. One CTA per (bh, j); 512 threads (16 warps).
// K/V loaded once; 4 x 64-row Q subtiles processed in-CTA.
// Strides: QSTR=73, VSTR=261 -> conflict-free transposed stores.
// s padded to 256 with zeroed K/V rows -> pad score cols exact 0.
// ---------------------------------------------------------------------------
#define ANP 256
#define QSTR 73
#define KSTR 68
#define VSTR 261
#define SSTR 260
#define ATTN_SMEM ((64*QSTR + ANP*KSTR + 64*VSTR + 64*SSTR) * 4)  // 221,760 B

__global__ __launch_bounds__(512, 1) void attn_kernel(
    const float* __restrict__ att_map, const float* __restrict__ wptr)
{
    extern __shared__ float sm[];
    unsigned* Qt = (unsigned*)sm;                 // [64][QSTR]
    unsigned* Ks = Qt + 64 * QSTR;                // [256][KSTR]
    unsigned* Vt = Ks + ANP * KSTR;               // [64][VSTR]
    float*    S  = (float*)(Vt + 64 * VSTR);      // [64][SSTR]

    int tid  = threadIdx.x;
    int warp = tid >> 5, lane = tid & 31;
    int gid  = lane >> 2, tig = lane & 3;

    int j  = blockIdx.x;
    int bh = blockIdx.y;

    size_t base = ((size_t)bh * J_ + j) * (size_t)(T_ * HD);
    const float* kp = g_qkv + (size_t)QS + base;
    const float* vp = g_qkv + (size_t)2 * QS + base;
    float wb = wptr[0];
    float one_minus = 1.f - wb;

    // ---- load K/V once (transposed V, conflict-free strides) ----
    for (int idx = tid; idx < ANP * HD; idx += 512) {
        int s = idx >> 6, d = idx & 63;
        float kv = (s < T_) ? kp[idx] : 0.f;
        float vv = (s < T_) ? vp[idx] : 0.f;
        Ks[s * KSTR + d] = f2tf32(kv);
        Vt[d * VSTR + s] = f2tf32(vv);
    }

    for (int rt = 0; rt < 4; rt++) {
        int r0 = rt * 64;
        int rows = min(64, T_ - r0);
        const float* qp = g_qkv + base + (size_t)r0 * HD;

        // ---- load Q subtile (transposed, conflict-free) ----
        for (int idx = tid; idx < 64 * HD; idx += 512) {
            int t = idx >> 6, d = idx & 63;
            float qv = (t < rows) ? qp[idx] : 0.f;
            Qt[d * QSTR + t] = f2tf32(qv);
        }
        __syncthreads();

        // ---- S = Q K^T * 0.125 : warps 4 in m (16) x 4 in n (64) ----
        {
            int wm = (warp & 3) * 16;
            int wn = (warp >> 2) * 64;
            float c[8][4];
#pragma unroll
            for (int nt = 0; nt < 8; nt++)
#pragma unroll
                for (int i = 0; i < 4; i++) c[nt][i] = 0.f;

#pragma unroll
            for (int k0 = 0; k0 < HD; k0 += 8) {
                int m = wm + gid;
                unsigned a0 = Qt[(k0 + tig)     * QSTR + m];
                unsigned a1 = Qt[(k0 + tig)     * QSTR + m + 8];
                unsigned a2 = Qt[(k0 + tig + 4) * QSTR + m];
                unsigned a3 = Qt[(k0 + tig + 4) * QSTR + m + 8];
#pragma unroll
                for (int nt = 0; nt < 8; nt++) {
                    int n = wn + nt * 8 + gid;
                    unsigned b0 = Ks[n * KSTR + k0 + tig];
                    unsigned b1 = Ks[n * KSTR + k0 + tig + 4];
                    mma_tf32(c[nt][0], c[nt][1], c[nt][2], c[nt][3],
                             a0, a1, a2, a3, b0, b1);
                }
            }
            const float scale = 0.125f;
            int m = wm + gid;
#pragma unroll
            for (int nt = 0; nt < 8; nt++) {
                int n = wn + nt * 8 + 2 * tig;
                *(float2*)&S[m * SSTR + n] =
                    make_float2(c[nt][0] * scale, c[nt][1] * scale);
                *(float2*)&S[(m + 8) * SSTR + n] =
                    make_float2(c[nt][2] * scale, c[nt][3] * scale);
            }
        }
        __syncthreads();

        // ---- softmax + blend (warp per row; 16 warps) ----
        for (int r = warp; r < rows; r += 16) {
            float* Sr = S + r * SSTR;
            float mx = -1e30f;
            for (int c2 = lane; c2 < T_; c2 += 32) mx = fmaxf(mx, Sr[c2]);
#pragma unroll
            for (int o = 16; o; o >>= 1) mx = fmaxf(mx, __shfl_xor_sync(0xffffffffu, mx, o));
            float sum = 0.f;
            for (int c2 = lane; c2 < T_; c2 += 32) {
                float e = __expf(Sr[c2] - mx);
                Sr[c2] = e;
                sum += e;
            }
#pragma unroll
            for (int o = 16; o; o >>= 1) sum += __shfl_xor_sync(0xffffffffu, sum, o);
            float inv = wb / sum;
            const float* am = att_map + (((size_t)bh * J_ + j) * T_ + (r0 + r)) * (size_t)T_;
            for (int c2 = lane; c2 < T_; c2 += 32)
                Sr[c2] = Sr[c2] * inv + one_minus * am[c2];
        }
        __syncthreads();

        // ---- out = S @ V : warps 4 in m (16) x 4 in n (16) ----
        {
            int wm = (warp & 3) * 16;
            int wn = (warp >> 2) * 16;
            float c[2][4];
#pragma unroll
            for (int nt = 0; nt < 2; nt++)
#pragma unroll
                for (int i = 0; i < 4; i++) c[nt][i] = 0.f;

#pragma unroll 4
            for (int k0 = 0; k0 < ANP; k0 += 8) {
                int m = wm + gid;
                unsigned a0 = f2tf32(S[m * SSTR + k0 + tig]);
                unsigned a1 = f2tf32(S[(m + 8) * SSTR + k0 + tig]);
                unsigned a2 = f2tf32(S[m * SSTR + k0 + tig + 4]);
                unsigned a3 = f2tf32(S[(m + 8) * SSTR + k0 + tig + 4]);
#pragma unroll
                for (int nt = 0; nt < 2; nt++) {
                    int n = wn + nt * 8 + gid;
                    unsigned b0 = Vt[n * VSTR + k0 + tig];
                    unsigned b1 = Vt[n * VSTR + k0 + tig + 4];
                    mma_tf32(c[nt][0], c[nt][1], c[nt][2], c[nt][3],
                             a0, a1, a2, a3, b0, b1);
                }
            }

            int b = bh >> 3, h = bh & 7;
            int t1 = r0 + wm + gid;
            int t2 = t1 + 8;
#pragma unroll
            for (int nt = 0; nt < 2; nt++) {
                int col = h * HD + wn + nt * 8 + 2 * tig;
                if (t1 < T_) {
                    float* op = g_att + (((size_t)(b * T_ + t1)) * J_ + j) * C_ + col;
                    *(float2*)op = make_float2(c[nt][0], c[nt][1]);
                }
                if (t2 < T_) {
                    float* op = g_att + (((size_t)(b * T_ + t2)) * J_ + j) * C_ + col;
                    *(float2*)op = make_float2(c[nt][2], c[nt][3]);
                }
            }
        }
        __syncthreads();
    }
}

// ---------------------------------------------------------------------------
extern "C" void kernel_launch(void* const* d_in, const int* in_sizes, int n_in,
                              void* d_out, int out_size)
{
    const float* x      = (const float*)d_in[0];
    const float* attmap = (const float*)d_in[1];
    const float* weight = (const float*)d_in[2];
    const float* W_qkv  = (const float*)d_in[3];
    const float* W_proj = (const float*)d_in[4];
    const float* b_proj = (const float*)d_in[5];
    float* out = (float*)d_out;

    cudaFuncSetAttribute(attn_kernel,
                         cudaFuncAttributeMaxDynamicSharedMemorySize, ATTN_SMEM);

    dim3 g1(3 * C_ / 128, (MROWS + 127) / 128);
    mma_gemm<<<g1, 256>>>(x, W_qkv, nullptr, nullptr, MROWS, 3 * C_, C_, 0);

    dim3 g2(J_, B_ * H_);
    attn_kernel<<<g2, 512, ATTN_SMEM>>>(attmap, weight);

    dim3 g3(C_ / 128, (MROWS + 127) / 128);
    mma_gemm<<<g3, 256>>>(nullptr, W_proj, b_proj, out, MROWS, C_, C_, 1);
}

// round 6
// speedup vs baseline: 3.1653x; 1.0164x over previous
#include <cuda_runtime.h>
#include <cstdint>

#define B_  8
#define T_  243
#define J_  17
#define H_  8
#define HD  64
#define C_  512
#define KDIM 512
#define MROWS (B_*T_*J_)            // 33048
#define QSZ (MROWS*KDIM)            // 16920576

// g_qkv: three row-major [MROWS][512] matrices (q,k,v); row r=(b*T+t)*J+j, col h*64+d
__device__ float g_qkv[3*QSZ];
__device__ float g_att[QSZ];        // [MROWS][512]

__device__ __forceinline__ unsigned f2tf32(float x) {
    unsigned r;
    asm("cvt.rna.tf32.f32 %0, %1;" : "=r"(r) : "f"(x));
    return r;
}

__device__ __forceinline__ void mma_tf32(
    float& c0, float& c1, float& c2, float& c3,
    unsigned a0, unsigned a1, unsigned a2, unsigned a3,
    unsigned b0, unsigned b1)
{
    asm volatile(
        "mma.sync.aligned.m16n8k8.row.col.f32.tf32.tf32.f32 "
        "{%0,%1,%2,%3}, {%4,%5,%6,%7}, {%8,%9}, {%0,%1,%2,%3};"
        : "+f"(c0), "+f"(c1), "+f"(c2), "+f"(c3)
        : "r"(a0), "r"(a1), "r"(a2), "r"(a3), "r"(b0), "r"(b1));
}

// ---------------------------------------------------------------------------
// tf32 GEMM: CTA 128x256, BK=16, 256 threads, 8 warps of 64x64.
// mode 0: x @ W_qkv -> g_qkv (which = col/512)   grid (6, 259)
// mode 1: g_att @ W_proj + bias -> Cout          grid (2, 259)
// ---------------------------------------------------------------------------
#define SKA 136
#define SKB 264

__global__ __launch_bounds__(256, 1) void mma_gemm(
    const float* __restrict__ Ain, const float* __restrict__ Bm,
    const float* __restrict__ bias, float* __restrict__ Cout,
    int N, int mode)
{
    __shared__ unsigned As[16 * SKA];
    __shared__ unsigned Bs[16 * SKB];

    int tid  = threadIdx.x;
    int warp = tid >> 5, lane = tid & 31;
    int gid  = lane >> 2, tig = lane & 3;
    int wm   = (warp & 1) * 64;
    int wn   = (warp >> 1) * 64;
    int row0 = blockIdx.y * 128;
    int col0 = blockIdx.x * 256;

    const float* A = (mode == 1) ? g_att : Ain;

    // A staging: row=tid/2, col=(tid&1)*8 -> 2 float4
    int arow = tid >> 1, acol = (tid & 1) * 8;
    // B staging: col=(tid&63)*4, rows tid>>6 + {0,4,8,12} -> 4 float4
    int bcol = (tid & 63) * 4, brow = tid >> 6;

    const float* Ag = A  + (size_t)(row0 + arow) * KDIM + acol;
    const float* Bg = Bm + (size_t)brow * N + col0 + bcol;
    bool aok = (row0 + arow) < MROWS;

    float c[4][8][4];
#pragma unroll
    for (int mt = 0; mt < 4; mt++)
#pragma unroll
        for (int nt = 0; nt < 8; nt++)
#pragma unroll
            for (int i = 0; i < 4; i++) c[mt][nt][i] = 0.f;

    float4 pa0, pa1, pb[4];
    pa0 = aok ? *(const float4*)Ag       : make_float4(0,0,0,0);
    pa1 = aok ? *(const float4*)(Ag + 4) : make_float4(0,0,0,0);
#pragma unroll
    for (int i = 0; i < 4; i++) pb[i] = *(const float4*)(Bg + (size_t)(4*i) * N);

    for (int k0 = 0; k0 < KDIM; k0 += 16) {
        As[(acol + 0) * SKA + arow] = f2tf32(pa0.x);
        As[(acol + 1) * SKA + arow] = f2tf32(pa0.y);
        As[(acol + 2) * SKA + arow] = f2tf32(pa0.z);
        As[(acol + 3) * SKA + arow] = f2tf32(pa0.w);
        As[(acol + 4) * SKA + arow] = f2tf32(pa1.x);
        As[(acol + 5) * SKA + arow] = f2tf32(pa1.y);
        As[(acol + 6) * SKA + arow] = f2tf32(pa1.z);
        As[(acol + 7) * SKA + arow] = f2tf32(pa1.w);
#pragma unroll
        for (int i = 0; i < 4; i++) {
            uint4 u = make_uint4(f2tf32(pb[i].x), f2tf32(pb[i].y),
                                 f2tf32(pb[i].z), f2tf32(pb[i].w));
            *(uint4*)&Bs[(brow + 4*i) * SKB + bcol] = u;
        }
        __syncthreads();

        if (k0 + 16 < KDIM) {
            Ag += 16;
            Bg += (size_t)16 * N;
            pa0 = aok ? *(const float4*)Ag       : make_float4(0,0,0,0);
            pa1 = aok ? *(const float4*)(Ag + 4) : make_float4(0,0,0,0);
#pragma unroll
            for (int i = 0; i < 4; i++) pb[i] = *(const float4*)(Bg + (size_t)(4*i) * N);
        }

#pragma unroll
        for (int ks = 0; ks < 16; ks += 8) {
            unsigned af[4][4], bf[8][2];
#pragma unroll
            for (int mt = 0; mt < 4; mt++) {
                int m = wm + mt * 16 + gid;
                af[mt][0] = As[(ks + tig)     * SKA + m];
                af[mt][1] = As[(ks + tig)     * SKA + m + 8];
                af[mt][2] = As[(ks + tig + 4) * SKA + m];
                af[mt][3] = As[(ks + tig + 4) * SKA + m + 8];
            }
#pragma unroll
            for (int nt = 0; nt < 8; nt++) {
                int n = wn + nt * 8 + gid;
                bf[nt][0] = Bs[(ks + tig)     * SKB + n];
                bf[nt][1] = Bs[(ks + tig + 4) * SKB + n];
            }
#pragma unroll
            for (int mt = 0; mt < 4; mt++)
#pragma unroll
                for (int nt = 0; nt < 8; nt++)
                    mma_tf32(c[mt][nt][0], c[mt][nt][1], c[mt][nt][2], c[mt][nt][3],
                             af[mt][0], af[mt][1], af[mt][2], af[mt][3],
                             bf[nt][0], bf[nt][1]);
        }
        __syncthreads();
    }

    if (mode == 0) {
#pragma unroll
        for (int mt = 0; mt < 4; mt++) {
            int rbase = row0 + wm + mt * 16 + gid;
#pragma unroll
            for (int half = 0; half < 2; half++) {
                int r = rbase + half * 8;
                if (r < MROWS) {
#pragma unroll
                    for (int nt = 0; nt < 8; nt++) {
                        int cb = col0 + wn + nt * 8 + 2 * tig;
                        int which = cb >> 9;
                        float* p = g_qkv + (size_t)which * QSZ +
                                   (size_t)r * 512 + (cb & 511);
                        *(float2*)p = half ? make_float2(c[mt][nt][2], c[mt][nt][3])
                                           : make_float2(c[mt][nt][0], c[mt][nt][1]);
                    }
                }
            }
        }
    } else {
#pragma unroll
        for (int mt = 0; mt < 4; mt++) {
            int r1 = row0 + wm + mt * 16 + gid;
            int r2 = r1 + 8;
#pragma unroll
            for (int nt = 0; nt < 8; nt++) {
                int cb = col0 + wn + nt * 8 + 2 * tig;
                float2 bb = *(const float2*)&bias[cb];
                if (r1 < MROWS)
                    *(float2*)&Cout[(size_t)r1 * 512 + cb] =
                        make_float2(c[mt][nt][0] + bb.x, c[mt][nt][1] + bb.y);
                if (r2 < MROWS)
                    *(float2*)&Cout[(size_t)r2 * 512 + cb] =
                        make_float2(c[mt][nt][2] + bb.x, c[mt][nt][3] + bb.y);
            }
        }
    }
}

// ---------------------------------------------------------------------------
// tf32 mma.sync attention. One CTA per (bh, j); 512 threads (16 warps).
// K/V loaded once; 4 x 64-row Q subtiles.  QK^T warps: 2m x 8n (32x32 tiles).
// g_qkv row layout: r=(b*T+t)*J+j, col h*64+d; stride between t = J*512.
// ---------------------------------------------------------------------------
#define ANP 256
#define QSTR 73
#define KSTR 68
#define VSTR 261
#define SSTR 260
#define ATTN_SMEM ((64*QSTR + ANP*KSTR + 64*VSTR + 64*SSTR) * 4)  // 221,760

__global__ __launch_bounds__(512, 1) void attn_kernel(
    const float* __restrict__ att_map, const float* __restrict__ wptr)
{
    extern __shared__ float sm[];
    unsigned* Qt = (unsigned*)sm;
    unsigned* Ks = Qt + 64 * QSTR;
    unsigned* Vt = Ks + ANP * KSTR;
    float*    S  = (float*)(Vt + 64 * VSTR);

    int tid  = threadIdx.x;
    int warp = tid >> 5, lane = tid & 31;
    int gid  = lane >> 2, tig = lane & 3;

    int j  = blockIdx.x;
    int bh = blockIdx.y;
    int b = bh >> 3, h = bh & 7;

    const size_t JC = (size_t)J_ * C_;
    size_t rowbase = ((size_t)b * T_) * JC + (size_t)j * C_ + h * HD;
    const float* qp0 = g_qkv + rowbase;
    const float* kp0 = g_qkv + (size_t)QSZ + rowbase;
    const float* vp0 = g_qkv + (size_t)2 * QSZ + rowbase;
    float wb = wptr[0];
    float one_minus = 1.f - wb;

    for (int idx = tid; idx < ANP * HD; idx += 512) {
        int s = idx >> 6, d = idx & 63;
        float kv = (s < T_) ? kp0[(size_t)s * JC + d] : 0.f;
        float vv = (s < T_) ? vp0[(size_t)s * JC + d] : 0.f;
        Ks[s * KSTR + d] = f2tf32(kv);
        Vt[d * VSTR + s] = f2tf32(vv);
    }

    for (int rt = 0; rt < 4; rt++) {
        int r0 = rt * 64;
        int rows = min(64, T_ - r0);

        for (int idx = tid; idx < 64 * HD; idx += 512) {
            int t = idx >> 6, d = idx & 63;
            float qv = (t < rows) ? qp0[(size_t)(r0 + t) * JC + d] : 0.f;
            Qt[d * QSTR + t] = f2tf32(qv);
        }
        __syncthreads();

        // ---- S = Q K^T * 0.125 : 16 warps as 2m x 8n, 32x32 tiles ----
        {
            int wm = (warp & 1) * 32;
            int wn = (warp >> 1) * 32;
            float c[2][4][4];
#pragma unroll
            for (int mt = 0; mt < 2; mt++)
#pragma unroll
                for (int nt = 0; nt < 4; nt++)
#pragma unroll
                    for (int i = 0; i < 4; i++) c[mt][nt][i] = 0.f;

#pragma unroll
            for (int k0 = 0; k0 < HD; k0 += 8) {
                unsigned a[2][4];
#pragma unroll
                for (int mt = 0; mt < 2; mt++) {
                    int m = wm + mt * 16 + gid;
                    a[mt][0] = Qt[(k0 + tig)     * QSTR + m];
                    a[mt][1] = Qt[(k0 + tig)     * QSTR + m + 8];
                    a[mt][2] = Qt[(k0 + tig + 4) * QSTR + m];
                    a[mt][3] = Qt[(k0 + tig + 4) * QSTR + m + 8];
                }
#pragma unroll
                for (int nt = 0; nt < 4; nt++) {
                    int n = wn + nt * 8 + gid;
                    unsigned b0 = Ks[n * KSTR + k0 + tig];
                    unsigned b1 = Ks[n * KSTR + k0 + tig + 4];
#pragma unroll
                    for (int mt = 0; mt < 2; mt++)
                        mma_tf32(c[mt][nt][0], c[mt][nt][1], c[mt][nt][2], c[mt][nt][3],
                                 a[mt][0], a[mt][1], a[mt][2], a[mt][3], b0, b1);
                }
            }
            const float scale = 0.125f;
#pragma unroll
            for (int mt = 0; mt < 2; mt++) {
                int m = wm + mt * 16 + gid;
#pragma unroll
                for (int nt = 0; nt < 4; nt++) {
                    int n = wn + nt * 8 + 2 * tig;
                    *(float2*)&S[m * SSTR + n] =
                        make_float2(c[mt][nt][0] * scale, c[mt][nt][1] * scale);
                    *(float2*)&S[(m + 8) * SSTR + n] =
                        make_float2(c[mt][nt][2] * scale, c[mt][nt][3] * scale);
                }
            }
        }
        __syncthreads();

        // ---- softmax + blend ----
        for (int r = warp; r < rows; r += 16) {
            float* Sr = S + r * SSTR;
            float mx = -1e30f;
            for (int c2 = lane; c2 < T_; c2 += 32) mx = fmaxf(mx, Sr[c2]);
#pragma unroll
            for (int o = 16; o; o >>= 1) mx = fmaxf(mx, __shfl_xor_sync(0xffffffffu, mx, o));
            float sum = 0.f;
            for (int c2 = lane; c2 < T_; c2 += 32) {
                float e = __expf(Sr[c2] - mx);
                Sr[c2] = e;
                sum += e;
            }
#pragma unroll
            for (int o = 16; o; o >>= 1) sum += __shfl_xor_sync(0xffffffffu, sum, o);
            float inv = wb / sum;
            const float* am = att_map + (((size_t)bh * J_ + j) * T_ + (r0 + r)) * (size_t)T_;
            for (int c2 = lane; c2 < T_; c2 += 32)
                Sr[c2] = Sr[c2] * inv + one_minus * am[c2];
        }
        __syncthreads();

        // ---- out = S @ V : warps 4m x 4n (16x16 tiles) ----
        {
            int wm = (warp & 3) * 16;
            int wn = (warp >> 2) * 16;
            float c[2][4];
#pragma unroll
            for (int nt = 0; nt < 2; nt++)
#pragma unroll
                for (int i = 0; i < 4; i++) c[nt][i] = 0.f;

#pragma unroll 4
            for (int k0 = 0; k0 < ANP; k0 += 8) {
                int m = wm + gid;
                unsigned a0 = f2tf32(S[m * SSTR + k0 + tig]);
                unsigned a1 = f2tf32(S[(m + 8) * SSTR + k0 + tig]);
                unsigned a2 = f2tf32(S[m * SSTR + k0 + tig + 4]);
                unsigned a3 = f2tf32(S[(m + 8) * SSTR + k0 + tig + 4]);
#pragma unroll
                for (int nt = 0; nt < 2; nt++) {
                    int n = wn + nt * 8 + gid;
                    unsigned b0 = Vt[n * VSTR + k0 + tig];
                    unsigned b1 = Vt[n * VSTR + k0 + tig + 4];
                    mma_tf32(c[nt][0], c[nt][1], c[nt][2], c[nt][3],
                             a0, a1, a2, a3, b0, b1);
                }
            }

            int t1 = r0 + wm + gid;
            int t2 = t1 + 8;
#pragma unroll
            for (int nt = 0; nt < 2; nt++) {
                int col = h * HD + wn + nt * 8 + 2 * tig;
                if (t1 < T_) {
                    float* op = g_att + (((size_t)(b * T_ + t1)) * J_ + j) * C_ + col;
                    *(float2*)op = make_float2(c[nt][0], c[nt][1]);
                }
                if (t2 < T_) {
                    float* op = g_att + (((size_t)(b * T_ + t2)) * J_ + j) * C_ + col;
                    *(float2*)op = make_float2(c[nt][2], c[nt][3]);
                }
            }
        }
        __syncthreads();
    }
}

// ---------------------------------------------------------------------------
extern "C" void kernel_launch(void* const* d_in, const int* in_sizes, int n_in,
                              void* d_out, int out_size)
{
    const float* x      = (const float*)d_in[0];
    const float* attmap = (const float*)d_in[1];
    const float* weight = (const float*)d_in[2];
    const float* W_qkv  = (const float*)d_in[3];
    const float* W_proj = (const float*)d_in[4];
    const float* b_proj = (const float*)d_in[5];
    float* out = (float*)d_out;

    cudaFuncSetAttribute(attn_kernel,
                         cudaFuncAttributeMaxDynamicSharedMemorySize, ATTN_SMEM);

    // 1) qkv projection -> g_qkv [which][r][512]
    dim3 g1(1536 / 256, (MROWS + 127) / 128);
    mma_gemm<<<g1, 256>>>(x, W_qkv, nullptr, nullptr, 1536, 0);

    // 2) attention
    dim3 g2(J_, B_ * H_);
    attn_kernel<<<g2, 512, ATTN_SMEM>>>(attmap, weight);

    // 3) output projection
    dim3 g3(512 / 256, (MROWS + 127) / 128);
    mma_gemm<<<g3, 256>>>(nullptr, W_proj, b_proj, out, 512, 1);
}

// round 7
// speedup vs baseline: 3.7487x; 1.1843x over previous
#include <cuda_runtime.h>
#include <cstdint>

#define B_  8
#define T_  243
#define J_  17
#define H_  8
#define HD  64
#define C_  512
#define KDIM 512
#define MROWS (B_*T_*J_)            // 33048
#define QSZ (MROWS*KDIM)            // 16920576

// g_qkv: three row-major [MROWS][512] matrices (q,k,v); row r=(b*T+t)*J+j, col h*64+d
__device__ float g_qkv[3*QSZ];
__device__ float g_att[QSZ];        // [MROWS][512]

__device__ __forceinline__ unsigned f2tf32(float x) {
    unsigned r;
    asm("cvt.rna.tf32.f32 %0, %1;" : "=r"(r) : "f"(x));
    return r;
}

__device__ __forceinline__ void mma_tf32(
    float& c0, float& c1, float& c2, float& c3,
    unsigned a0, unsigned a1, unsigned a2, unsigned a3,
    unsigned b0, unsigned b1)
{
    asm volatile(
        "mma.sync.aligned.m16n8k8.row.col.f32.tf32.tf32.f32 "
        "{%0,%1,%2,%3}, {%4,%5,%6,%7}, {%8,%9}, {%0,%1,%2,%3};"
        : "+f"(c0), "+f"(c1), "+f"(c2), "+f"(c3)
        : "r"(a0), "r"(a1), "r"(a2), "r"(a3), "r"(b0), "r"(b1));
}

// ---------------------------------------------------------------------------
// tf32 GEMM: CTA 128x256, BK=16, 256 threads, 8 warps of 64x64.
// Double-buffered smem; one __syncthreads per k-iter.
// mode 0: x @ W_qkv -> g_qkv (which = col/512)   grid (6, 259)
// mode 1: g_att @ W_proj + bias -> Cout          grid (2, 259)
// ---------------------------------------------------------------------------
#define SKA 136
#define SKB 264
#define ASTAGE (16 * SKA)
#define BSTAGE (16 * SKB)

__global__ __launch_bounds__(256, 1) void mma_gemm(
    const float* __restrict__ Ain, const float* __restrict__ Bm,
    const float* __restrict__ bias, float* __restrict__ Cout,
    int N, int mode)
{
    __shared__ unsigned As[2 * ASTAGE];
    __shared__ unsigned Bs[2 * BSTAGE];

    int tid  = threadIdx.x;
    int warp = tid >> 5, lane = tid & 31;
    int gid  = lane >> 2, tig = lane & 3;
    int wm   = (warp & 1) * 64;
    int wn   = (warp >> 1) * 64;
    int row0 = blockIdx.y * 128;
    int col0 = blockIdx.x * 256;

    const float* A = (mode == 1) ? g_att : Ain;

    int arow = tid >> 1, acol = (tid & 1) * 8;
    int bcol = (tid & 63) * 4, brow = tid >> 6;

    const float* Ag = A  + (size_t)(row0 + arow) * KDIM + acol;
    const float* Bg = Bm + (size_t)brow * N + col0 + bcol;
    bool aok = (row0 + arow) < MROWS;

    float c[4][8][4];
#pragma unroll
    for (int mt = 0; mt < 4; mt++)
#pragma unroll
        for (int nt = 0; nt < 8; nt++)
#pragma unroll
            for (int i = 0; i < 4; i++) c[mt][nt][i] = 0.f;

    float4 pa0, pa1, pb[4];

    // store regs -> stage s
    auto stage_store = [&](int s) {
        unsigned* Ap = As + s * ASTAGE;
        unsigned* Bp = Bs + s * BSTAGE;
        Ap[(acol + 0) * SKA + arow] = f2tf32(pa0.x);
        Ap[(acol + 1) * SKA + arow] = f2tf32(pa0.y);
        Ap[(acol + 2) * SKA + arow] = f2tf32(pa0.z);
        Ap[(acol + 3) * SKA + arow] = f2tf32(pa0.w);
        Ap[(acol + 4) * SKA + arow] = f2tf32(pa1.x);
        Ap[(acol + 5) * SKA + arow] = f2tf32(pa1.y);
        Ap[(acol + 6) * SKA + arow] = f2tf32(pa1.z);
        Ap[(acol + 7) * SKA + arow] = f2tf32(pa1.w);
#pragma unroll
        for (int i = 0; i < 4; i++) {
            uint4 u = make_uint4(f2tf32(pb[i].x), f2tf32(pb[i].y),
                                 f2tf32(pb[i].z), f2tf32(pb[i].w));
            *(uint4*)&Bp[(brow + 4*i) * SKB + bcol] = u;
        }
    };
    auto gload = [&]() {
        pa0 = aok ? *(const float4*)Ag       : make_float4(0,0,0,0);
        pa1 = aok ? *(const float4*)(Ag + 4) : make_float4(0,0,0,0);
#pragma unroll
        for (int i = 0; i < 4; i++) pb[i] = *(const float4*)(Bg + (size_t)(4*i) * N);
    };

    // prologue: chunk0 -> stage0; prefetch chunk1 into regs
    gload();
    stage_store(0);
    Ag += 16; Bg += (size_t)16 * N;
    gload();
    __syncthreads();

    const int NITER = KDIM / 16;   // 32
    int s = 0;
    for (int i = 0; i < NITER; i++) {
        // compute from stage s
        const unsigned* Ap = As + s * ASTAGE;
        const unsigned* Bp = Bs + s * BSTAGE;
#pragma unroll
        for (int ks = 0; ks < 16; ks += 8) {
            unsigned af[4][4], bf[8][2];
#pragma unroll
            for (int mt = 0; mt < 4; mt++) {
                int m = wm + mt * 16 + gid;
                af[mt][0] = Ap[(ks + tig)     * SKA + m];
                af[mt][1] = Ap[(ks + tig)     * SKA + m + 8];
                af[mt][2] = Ap[(ks + tig + 4) * SKA + m];
                af[mt][3] = Ap[(ks + tig + 4) * SKA + m + 8];
            }
#pragma unroll
            for (int nt = 0; nt < 8; nt++) {
                int n = wn + nt * 8 + gid;
                bf[nt][0] = Bp[(ks + tig)     * SKB + n];
                bf[nt][1] = Bp[(ks + tig + 4) * SKB + n];
            }
#pragma unroll
            for (int mt = 0; mt < 4; mt++)
#pragma unroll
                for (int nt = 0; nt < 8; nt++)
                    mma_tf32(c[mt][nt][0], c[mt][nt][1], c[mt][nt][2], c[mt][nt][3],
                             af[mt][0], af[mt][1], af[mt][2], af[mt][3],
                             bf[nt][0], bf[nt][1]);
        }

        if (i + 1 < NITER) {
            stage_store(s ^ 1);                 // regs hold chunk i+1
            if (i + 2 < NITER) {
                Ag += 16; Bg += (size_t)16 * N;
                gload();                         // chunk i+2 in flight
            }
        }
        __syncthreads();
        s ^= 1;
    }

    if (mode == 0) {
#pragma unroll
        for (int mt = 0; mt < 4; mt++) {
            int rbase = row0 + wm + mt * 16 + gid;
#pragma unroll
            for (int half = 0; half < 2; half++) {
                int r = rbase + half * 8;
                if (r < MROWS) {
#pragma unroll
                    for (int nt = 0; nt < 8; nt++) {
                        int cb = col0 + wn + nt * 8 + 2 * tig;
                        int which = cb >> 9;
                        float* p = g_qkv + (size_t)which * QSZ +
                                   (size_t)r * 512 + (cb & 511);
                        *(float2*)p = half ? make_float2(c[mt][nt][2], c[mt][nt][3])
                                           : make_float2(c[mt][nt][0], c[mt][nt][1]);
                    }
                }
            }
        }
    } else {
#pragma unroll
        for (int mt = 0; mt < 4; mt++) {
            int r1 = row0 + wm + mt * 16 + gid;
            int r2 = r1 + 8;
#pragma unroll
            for (int nt = 0; nt < 8; nt++) {
                int cb = col0 + wn + nt * 8 + 2 * tig;
                float2 bb = *(const float2*)&bias[cb];
                if (r1 < MROWS)
                    *(float2*)&Cout[(size_t)r1 * 512 + cb] =
                        make_float2(c[mt][nt][0] + bb.x, c[mt][nt][1] + bb.y);
                if (r2 < MROWS)
                    *(float2*)&Cout[(size_t)r2 * 512 + cb] =
                        make_float2(c[mt][nt][2] + bb.x, c[mt][nt][3] + bb.y);
            }
        }
    }
}

// ---------------------------------------------------------------------------
// tf32 mma.sync attention. One CTA per (bh, j); 512 threads (16 warps).
// K/V loaded once; 4 x 64-row Q subtiles.  QK^T warps: 2m x 8n (32x32 tiles).
// ---------------------------------------------------------------------------
#define ANP 256
#define QSTR 73
#define KSTR 68
#define VSTR 261
#define SSTR 260
#define ATTN_SMEM ((64*QSTR + ANP*KSTR + 64*VSTR + 64*SSTR) * 4)  // 221,760

__global__ __launch_bounds__(512, 1) void attn_kernel(
    const float* __restrict__ att_map, const float* __restrict__ wptr)
{
    extern __shared__ float sm[];
    unsigned* Qt = (unsigned*)sm;
    unsigned* Ks = Qt + 64 * QSTR;
    unsigned* Vt = Ks + ANP * KSTR;
    float*    S  = (float*)(Vt + 64 * VSTR);

    int tid  = threadIdx.x;
    int warp = tid >> 5, lane = tid & 31;
    int gid  = lane >> 2, tig = lane & 3;

    int j  = blockIdx.x;
    int bh = blockIdx.y;
    int b = bh >> 3, h = bh & 7;

    const size_t JC = (size_t)J_ * C_;
    size_t rowbase = ((size_t)b * T_) * JC + (size_t)j * C_ + h * HD;
    const float* qp0 = g_qkv + rowbase;
    const float* kp0 = g_qkv + (size_t)QSZ + rowbase;
    const float* vp0 = g_qkv + (size_t)2 * QSZ + rowbase;
    float wb = wptr[0];
    float one_minus = 1.f - wb;

    for (int idx = tid; idx < ANP * HD; idx += 512) {
        int s = idx >> 6, d = idx & 63;
        float kv = (s < T_) ? kp0[(size_t)s * JC + d] : 0.f;
        float vv = (s < T_) ? vp0[(size_t)s * JC + d] : 0.f;
        Ks[s * KSTR + d] = f2tf32(kv);
        Vt[d * VSTR + s] = f2tf32(vv);
    }

    for (int rt = 0; rt < 4; rt++) {
        int r0 = rt * 64;
        int rows = min(64, T_ - r0);

        for (int idx = tid; idx < 64 * HD; idx += 512) {
            int t = idx >> 6, d = idx & 63;
            float qv = (t < rows) ? qp0[(size_t)(r0 + t) * JC + d] : 0.f;
            Qt[d * QSTR + t] = f2tf32(qv);
        }
        __syncthreads();

        // ---- S = Q K^T * 0.125 : 16 warps as 2m x 8n, 32x32 tiles ----
        {
            int wm = (warp & 1) * 32;
            int wn = (warp >> 1) * 32;
            float c[2][4][4];
#pragma unroll
            for (int mt = 0; mt < 2; mt++)
#pragma unroll
                for (int nt = 0; nt < 4; nt++)
#pragma unroll
                    for (int i = 0; i < 4; i++) c[mt][nt][i] = 0.f;

#pragma unroll
            for (int k0 = 0; k0 < HD; k0 += 8) {
                unsigned a[2][4];
#pragma unroll
                for (int mt = 0; mt < 2; mt++) {
                    int m = wm + mt * 16 + gid;
                    a[mt][0] = Qt[(k0 + tig)     * QSTR + m];
                    a[mt][1] = Qt[(k0 + tig)     * QSTR + m + 8];
                    a[mt][2] = Qt[(k0 + tig + 4) * QSTR + m];
                    a[mt][3] = Qt[(k0 + tig + 4) * QSTR + m + 8];
                }
#pragma unroll
                for (int nt = 0; nt < 4; nt++) {
                    int n = wn + nt * 8 + gid;
                    unsigned b0 = Ks[n * KSTR + k0 + tig];
                    unsigned b1 = Ks[n * KSTR + k0 + tig + 4];
#pragma unroll
                    for (int mt = 0; mt < 2; mt++)
                        mma_tf32(c[mt][nt][0], c[mt][nt][1], c[mt][nt][2], c[mt][nt][3],
                                 a[mt][0], a[mt][1], a[mt][2], a[mt][3], b0, b1);
                }
            }
            const float scale = 0.125f;
#pragma unroll
            for (int mt = 0; mt < 2; mt++) {
                int m = wm + mt * 16 + gid;
#pragma unroll
                for (int nt = 0; nt < 4; nt++) {
                    int n = wn + nt * 8 + 2 * tig;
                    *(float2*)&S[m * SSTR + n] =
                        make_float2(c[mt][nt][0] * scale, c[mt][nt][1] * scale);
                    *(float2*)&S[(m + 8) * SSTR + n] =
                        make_float2(c[mt][nt][2] * scale, c[mt][nt][3] * scale);
                }
            }
        }
        __syncthreads();

        // ---- softmax + blend (att_map prefetched into regs first) ----
        for (int r = warp; r < rows; r += 16) {
            float* Sr = S + r * SSTR;
            const float* am = att_map + (((size_t)bh * J_ + j) * T_ + (r0 + r)) * (size_t)T_;
            float amv[8];
#pragma unroll
            for (int i = 0; i < 8; i++) {
                int c2 = lane + 32 * i;
                amv[i] = (c2 < T_) ? am[c2] : 0.f;
            }
            float mx = -1e30f;
            for (int c2 = lane; c2 < T_; c2 += 32) mx = fmaxf(mx, Sr[c2]);
#pragma unroll
            for (int o = 16; o; o >>= 1) mx = fmaxf(mx, __shfl_xor_sync(0xffffffffu, mx, o));
            float sum = 0.f;
            for (int c2 = lane; c2 < T_; c2 += 32) {
                float e = __expf(Sr[c2] - mx);
                Sr[c2] = e;
                sum += e;
            }
#pragma unroll
            for (int o = 16; o; o >>= 1) sum += __shfl_xor_sync(0xffffffffu, sum, o);
            float inv = wb / sum;
#pragma unroll
            for (int i = 0; i < 8; i++) {
                int c2 = lane + 32 * i;
                if (c2 < T_)
                    Sr[c2] = Sr[c2] * inv + one_minus * amv[i];
            }
        }
        __syncthreads();

        // ---- out = S @ V : warps 4m x 4n (16x16 tiles) ----
        {
            int wm = (warp & 3) * 16;
            int wn = (warp >> 2) * 16;
            float c[2][4];
#pragma unroll
            for (int nt = 0; nt < 2; nt++)
#pragma unroll
                for (int i = 0; i < 4; i++) c[nt][i] = 0.f;

#pragma unroll 4
            for (int k0 = 0; k0 < ANP; k0 += 8) {
                int m = wm + gid;
                unsigned a0 = f2tf32(S[m * SSTR + k0 + tig]);
                unsigned a1 = f2tf32(S[(m + 8) * SSTR + k0 + tig]);
                unsigned a2 = f2tf32(S[m * SSTR + k0 + tig + 4]);
                unsigned a3 = f2tf32(S[(m + 8) * SSTR + k0 + tig + 4]);
#pragma unroll
                for (int nt = 0; nt < 2; nt++) {
                    int n = wn + nt * 8 + gid;
                    unsigned b0 = Vt[n * VSTR + k0 + tig];
                    unsigned b1 = Vt[n * VSTR + k0 + tig + 4];
                    mma_tf32(c[nt][0], c[nt][1], c[nt][2], c[nt][3],
                             a0, a1, a2, a3, b0, b1);
                }
            }

            int t1 = r0 + wm + gid;
            int t2 = t1 + 8;
#pragma unroll
            for (int nt = 0; nt < 2; nt++) {
                int col = h * HD + wn + nt * 8 + 2 * tig;
                if (t1 < T_) {
                    float* op = g_att + (((size_t)(b * T_ + t1)) * J_ + j) * C_ + col;
                    *(float2*)op = make_float2(c[nt][0], c[nt][1]);
                }
                if (t2 < T_) {
                    float* op = g_att + (((size_t)(b * T_ + t2)) * J_ + j) * C_ + col;
                    *(float2*)op = make_float2(c[nt][2], c[nt][3]);
                }
            }
        }
        __syncthreads();
    }
}

// ---------------------------------------------------------------------------
extern "C" void kernel_launch(void* const* d_in, const int* in_sizes, int n_in,
                              void* d_out, int out_size)
{
    const float* x      = (const float*)d_in[0];
    const float* attmap = (const float*)d_in[1];
    const float* weight = (const float*)d_in[2];
    const float* W_qkv  = (const float*)d_in[3];
    const float* W_proj = (const float*)d_in[4];
    const float* b_proj = (const float*)d_in[5];
    float* out = (float*)d_out;

    cudaFuncSetAttribute(attn_kernel,
                         cudaFuncAttributeMaxDynamicSharedMemorySize, ATTN_SMEM);

    dim3 g1(1536 / 256, (MROWS + 127) / 128);
    mma_gemm<<<g1, 256>>>(x, W_qkv, nullptr, nullptr, 1536, 0);

    dim3 g2(J_, B_ * H_);
    attn_kernel<<<g2, 512, ATTN_SMEM>>>(attmap, weight);

    dim3 g3(512 / 256, (MROWS + 127) / 128);
    mma_gemm<<<g3, 256>>>(nullptr, W_proj, b_proj, out, 512, 1);
}

// round 9
// speedup vs baseline: 3.9983x; 1.0666x over previous
#include <cuda_runtime.h>
#include <cstdint>

#define B_  8
#define T_  243
#define J_  17
#define H_  8
#define HD  64
#define C_  512
#define KDIM 512
#define MROWS (B_*T_*J_)            // 33048
#define QSZ (MROWS*KDIM)            // 16920576

// g_qkv: three row-major [MROWS][512] matrices; row r=(b*T+t)*J+j, col h*64+d
__device__ float g_qkv[3*QSZ];
__device__ float g_att[QSZ];        // [MROWS][512], tf32-rounded by attention
__device__ float g_xr[QSZ];         // x pre-rounded to tf32
__device__ float g_wq[KDIM*1536];   // W_qkv rounded, [K][N] row-major
__device__ float g_wp[KDIM*512];    // W_proj rounded

__device__ __forceinline__ unsigned f2tf32(float x) {
    unsigned r;
    asm("cvt.rna.tf32.f32 %0, %1;" : "=r"(r) : "f"(x));
    return r;
}

__device__ __forceinline__ void mma_tf32(
    float& c0, float& c1, float& c2, float& c3,
    unsigned a0, unsigned a1, unsigned a2, unsigned a3,
    unsigned b0, unsigned b1)
{
    asm volatile(
        "mma.sync.aligned.m16n8k8.row.col.f32.tf32.tf32.f32 "
        "{%0,%1,%2,%3}, {%4,%5,%6,%7}, {%8,%9}, {%0,%1,%2,%3};"
        : "+f"(c0), "+f"(c1), "+f"(c2), "+f"(c3)
        : "r"(a0), "r"(a1), "r"(a2), "r"(a3), "r"(b0), "r"(b1));
}

__device__ __forceinline__ void cp16(uint32_t dst, const void* src, bool ok) {
    int sz = ok ? 16 : 0;
    asm volatile("cp.async.cg.shared.global [%0], [%1], 16, %2;"
                 :: "r"(dst), "l"(src), "r"(sz) : "memory");
}
__device__ __forceinline__ uint32_t smem_u32(const void* p) {
    uint32_t a;
    asm("{ .reg .u64 t; cvta.to.shared.u64 t, %1; cvt.u32.u64 %0, t; }" : "=r"(a) : "l"(p));
    return a;
}

// ---------------------------------------------------------------------------
// pre-rounding kernel
// ---------------------------------------------------------------------------
__global__ void round4(const float* __restrict__ in, float* __restrict__ outp, int n4) {
    int i = blockIdx.x * 256 + threadIdx.x;
    if (i < n4) {
        float4 v = ((const float4*)in)[i];
        v.x = __uint_as_float(f2tf32(v.x));
        v.y = __uint_as_float(f2tf32(v.y));
        v.z = __uint_as_float(f2tf32(v.z));
        v.w = __uint_as_float(f2tf32(v.w));
        ((float4*)outp)[i] = v;
    }
}

// ---------------------------------------------------------------------------
// tf32 GEMM, cp.async 3-stage: CTA 128x256, BK=32, 256 threads, 8 warps 64x64.
// A row-major [128][36], B row-major [32][264] per stage.
// mode 0: g_xr @ g_wq -> g_qkv (which = col/512)   grid (6, 259)
// mode 1: g_att @ g_wp + bias -> Cout              grid (2, 259)
// ---------------------------------------------------------------------------
#define ASTR 36
#define BSTR 264
#define ASTAGE_W (128*ASTR)          // words
#define BSTAGE_W (32*BSTR)
#define STAGE_W  (ASTAGE_W + BSTAGE_W)
#define GEMM_SMEM (3 * STAGE_W * 4)  // 156,672 B

__global__ __launch_bounds__(256, 1) void mma_gemm(
    const float* __restrict__ Ain, const float* __restrict__ Bm,
    const float* __restrict__ bias, float* __restrict__ Cout,
    int N, int mode)
{
    extern __shared__ unsigned smg[];

    int tid  = threadIdx.x;
    int warp = tid >> 5, lane = tid & 31;
    int gid  = lane >> 2, tig = lane & 3;
    int wm   = (warp & 1) * 64;
    int wn   = (warp >> 1) * 64;
    int row0 = blockIdx.y * 128;
    int col0 = blockIdx.x * 256;

    uint32_t smb = smem_u32(smg);

    const float* Abase = Ain + (size_t)row0 * KDIM;
    const float* Bbase = Bm + col0;

    auto load_stage = [&](int kc, int s) {
        uint32_t Ad = smb + s * STAGE_W * 4;
        uint32_t Bd = Ad + ASTAGE_W * 4;
#pragma unroll
        for (int t = 0; t < 4; t++) {
            int idx = tid + t * 256;
            int r = idx >> 3, cw = idx & 7;
            bool ok = (row0 + r) < MROWS;
            cp16(Ad + (r * ASTR + cw * 4) * 4,
                 Abase + (size_t)r * KDIM + kc * 32 + cw * 4, ok);
        }
#pragma unroll
        for (int t = 0; t < 8; t++) {
            int idx = tid + t * 256;
            int r = idx >> 6, cw = idx & 63;
            cp16(Bd + (r * BSTR + cw * 4) * 4,
                 Bbase + (size_t)(kc * 32 + r) * N + cw * 4, true);
        }
        asm volatile("cp.async.commit_group;" ::: "memory");
    };

    float c[4][8][4];
#pragma unroll
    for (int mt = 0; mt < 4; mt++)
#pragma unroll
        for (int nt = 0; nt < 8; nt++)
#pragma unroll
            for (int i = 0; i < 4; i++) c[mt][nt][i] = 0.f;

    const int NITER = KDIM / 32;     // 16
    load_stage(0, 0);
    load_stage(1, 1);

    for (int i = 0; i < NITER; i++) {
        if (i == NITER - 1) asm volatile("cp.async.wait_group 0;" ::: "memory");
        else                asm volatile("cp.async.wait_group 1;" ::: "memory");
        __syncthreads();

        int s = i % 3;
        const unsigned* Ap = smg + s * STAGE_W;
        const unsigned* Bp = Ap + ASTAGE_W;

#pragma unroll
        for (int ks = 0; ks < 32; ks += 8) {
            unsigned af[4][4], bf[8][2];
#pragma unroll
            for (int mt = 0; mt < 4; mt++) {
                int m = wm + mt * 16 + gid;
                af[mt][0] = Ap[m * ASTR + ks + tig];
                af[mt][1] = Ap[(m + 8) * ASTR + ks + tig];
                af[mt][2] = Ap[m * ASTR + ks + tig + 4];
                af[mt][3] = Ap[(m + 8) * ASTR + ks + tig + 4];
            }
#pragma unroll
            for (int nt = 0; nt < 8; nt++) {
                int n = wn + nt * 8 + gid;
                bf[nt][0] = Bp[(ks + tig) * BSTR + n];
                bf[nt][1] = Bp[(ks + tig + 4) * BSTR + n];
            }
#pragma unroll
            for (int mt = 0; mt < 4; mt++)
#pragma unroll
                for (int nt = 0; nt < 8; nt++)
                    mma_tf32(c[mt][nt][0], c[mt][nt][1], c[mt][nt][2], c[mt][nt][3],
                             af[mt][0], af[mt][1], af[mt][2], af[mt][3],
                             bf[nt][0], bf[nt][1]);
        }

        if (i + 2 < NITER) {
            __syncthreads();                 // stage (i+2)%3's previous compute done
            load_stage(i + 2, (i + 2) % 3);
        }
    }

    if (mode == 0) {
#pragma unroll
        for (int mt = 0; mt < 4; mt++) {
            int rbase = row0 + wm + mt * 16 + gid;
#pragma unroll
            for (int half = 0; half < 2; half++) {
                int r = rbase + half * 8;
                if (r < MROWS) {
#pragma unroll
                    for (int nt = 0; nt < 8; nt++) {
                        int cb = col0 + wn + nt * 8 + 2 * tig;
                        int which = cb >> 9;
                        float* p = g_qkv + (size_t)which * QSZ +
                                   (size_t)r * 512 + (cb & 511);
                        *(float2*)p = half ? make_float2(c[mt][nt][2], c[mt][nt][3])
                                           : make_float2(c[mt][nt][0], c[mt][nt][1]);
                    }
                }
            }
        }
    } else {
#pragma unroll
        for (int mt = 0; mt < 4; mt++) {
            int r1 = row0 + wm + mt * 16 + gid;
            int r2 = r1 + 8;
#pragma unroll
            for (int nt = 0; nt < 8; nt++) {
                int cb = col0 + wn + nt * 8 + 2 * tig;
                float2 bb = *(const float2*)&bias[cb];
                if (r1 < MROWS)
                    *(float2*)&Cout[(size_t)r1 * 512 + cb] =
                        make_float2(c[mt][nt][0] + bb.x, c[mt][nt][1] + bb.y);
                if (r2 < MROWS)
                    *(float2*)&Cout[(size_t)r2 * 512 + cb] =
                        make_float2(c[mt][nt][2] + bb.x, c[mt][nt][3] + bb.y);
            }
        }
    }
}

// ---------------------------------------------------------------------------
// tf32 mma.sync attention. One CTA per (bh, j); 512 threads (16 warps).
// ---------------------------------------------------------------------------
#define ANP 256
#define QSTR 73
#define KSTR 68
#define VSTR 261
#define SSTR 260
#define ATTN_SMEM ((64*QSTR + ANP*KSTR + 64*VSTR + 64*SSTR) * 4)  // 221,760

__global__ __launch_bounds__(512, 1) void attn_kernel(
    const float* __restrict__ att_map, const float* __restrict__ wptr)
{
    extern __shared__ float sm[];
    unsigned* Qt = (unsigned*)sm;
    unsigned* Ks = Qt + 64 * QSTR;
    unsigned* Vt = Ks + ANP * KSTR;
    float*    S  = (float*)(Vt + 64 * VSTR);

    int tid  = threadIdx.x;
    int warp = tid >> 5, lane = tid & 31;
    int gid  = lane >> 2, tig = lane & 3;

    int j  = blockIdx.x;
    int bh = blockIdx.y;
    int b = bh >> 3, h = bh & 7;

    const size_t JC = (size_t)J_ * C_;
    size_t rowbase = ((size_t)b * T_) * JC + (size_t)j * C_ + h * HD;
    const float* qp0 = g_qkv + rowbase;
    const float* kp0 = g_qkv + (size_t)QSZ + rowbase;
    const float* vp0 = g_qkv + (size_t)2 * QSZ + rowbase;
    float wb = wptr[0];
    float one_minus = 1.f - wb;

    for (int idx = tid; idx < ANP * HD; idx += 512) {
        int s = idx >> 6, d = idx & 63;
        float kv = (s < T_) ? kp0[(size_t)s * JC + d] : 0.f;
        float vv = (s < T_) ? vp0[(size_t)s * JC + d] : 0.f;
        Ks[s * KSTR + d] = f2tf32(kv);
        Vt[d * VSTR + s] = f2tf32(vv);
    }

    for (int rt = 0; rt < 4; rt++) {
        int r0 = rt * 64;
        int rows = min(64, T_ - r0);

        for (int idx = tid; idx < 64 * HD; idx += 512) {
            int t = idx >> 6, d = idx & 63;
            float qv = (t < rows) ? qp0[(size_t)(r0 + t) * JC + d] : 0.f;
            Qt[d * QSTR + t] = f2tf32(qv);
        }
        __syncthreads();

        // ---- S = Q K^T * 0.125 : 16 warps as 2m x 8n, 32x32 tiles ----
        {
            int wm = (warp & 1) * 32;
            int wn = (warp >> 1) * 32;
            float c[2][4][4];
#pragma unroll
            for (int mt = 0; mt < 2; mt++)
#pragma unroll
                for (int nt = 0; nt < 4; nt++)
#pragma unroll
                    for (int i = 0; i < 4; i++) c[mt][nt][i] = 0.f;

#pragma unroll
            for (int k0 = 0; k0 < HD; k0 += 8) {
                unsigned a[2][4];
#pragma unroll
                for (int mt = 0; mt < 2; mt++) {
                    int m = wm + mt * 16 + gid;
                    a[mt][0] = Qt[(k0 + tig)     * QSTR + m];
                    a[mt][1] = Qt[(k0 + tig)     * QSTR + m + 8];
                    a[mt][2] = Qt[(k0 + tig + 4) * QSTR + m];
                    a[mt][3] = Qt[(k0 + tig + 4) * QSTR + m + 8];
                }
#pragma unroll
                for (int nt = 0; nt < 4; nt++) {
                    int n = wn + nt * 8 + gid;
                    unsigned b0 = Ks[n * KSTR + k0 + tig];
                    unsigned b1 = Ks[n * KSTR + k0 + tig + 4];
#pragma unroll
                    for (int mt = 0; mt < 2; mt++)
                        mma_tf32(c[mt][nt][0], c[mt][nt][1], c[mt][nt][2], c[mt][nt][3],
                                 a[mt][0], a[mt][1], a[mt][2], a[mt][3], b0, b1);
                }
            }
            const float scale = 0.125f;
#pragma unroll
            for (int mt = 0; mt < 2; mt++) {
                int m = wm + mt * 16 + gid;
#pragma unroll
                for (int nt = 0; nt < 4; nt++) {
                    int n = wn + nt * 8 + 2 * tig;
                    *(float2*)&S[m * SSTR + n] =
                        make_float2(c[mt][nt][0] * scale, c[mt][nt][1] * scale);
                    *(float2*)&S[(m + 8) * SSTR + n] =
                        make_float2(c[mt][nt][2] * scale, c[mt][nt][3] * scale);
                }
            }
        }
        __syncthreads();

        // ---- softmax + blend (att_map prefetched into regs) ----
        for (int r = warp; r < rows; r += 16) {
            float* Sr = S + r * SSTR;
            const float* am = att_map + (((size_t)bh * J_ + j) * T_ + (r0 + r)) * (size_t)T_;
            float amv[8];
#pragma unroll
            for (int i = 0; i < 8; i++) {
                int c2 = lane + 32 * i;
                amv[i] = (c2 < T_) ? am[c2] : 0.f;
            }
            float mx = -1e30f;
            for (int c2 = lane; c2 < T_; c2 += 32) mx = fmaxf(mx, Sr[c2]);
#pragma unroll
            for (int o = 16; o; o >>= 1) mx = fmaxf(mx, __shfl_xor_sync(0xffffffffu, mx, o));
            float sum = 0.f;
            for (int c2 = lane; c2 < T_; c2 += 32) {
                float e = __expf(Sr[c2] - mx);
                Sr[c2] = e;
                sum += e;
            }
#pragma unroll
            for (int o = 16; o; o >>= 1) sum += __shfl_xor_sync(0xffffffffu, sum, o);
            float inv = wb / sum;
#pragma unroll
            for (int i = 0; i < 8; i++) {
                int c2 = lane + 32 * i;
                if (c2 < T_)
                    Sr[c2] = Sr[c2] * inv + one_minus * amv[i];
            }
        }
        __syncthreads();

        // ---- out = S @ V : warps 4m x 4n (16x16 tiles); round for GEMM2 ----
        {
            int wm = (warp & 3) * 16;
            int wn = (warp >> 2) * 16;
            float c[2][4];
#pragma unroll
            for (int nt = 0; nt < 2; nt++)
#pragma unroll
                for (int i = 0; i < 4; i++) c[nt][i] = 0.f;

#pragma unroll 4
            for (int k0 = 0; k0 < ANP; k0 += 8) {
                int m = wm + gid;
                unsigned a0 = f2tf32(S[m * SSTR + k0 + tig]);
                unsigned a1 = f2tf32(S[(m + 8) * SSTR + k0 + tig]);
                unsigned a2 = f2tf32(S[m * SSTR + k0 + tig + 4]);
                unsigned a3 = f2tf32(S[(m + 8) * SSTR + k0 + tig + 4]);
#pragma unroll
                for (int nt = 0; nt < 2; nt++) {
                    int n = wn + nt * 8 + gid;
                    unsigned b0 = Vt[n * VSTR + k0 + tig];
                    unsigned b1 = Vt[n * VSTR + k0 + tig + 4];
                    mma_tf32(c[nt][0], c[nt][1], c[nt][2], c[nt][3],
                             a0, a1, a2, a3, b0, b1);
                }
            }

            int t1 = r0 + wm + gid;
            int t2 = t1 + 8;
#pragma unroll
            for (int nt = 0; nt < 2; nt++) {
                int col = h * HD + wn + nt * 8 + 2 * tig;
                if (t1 < T_) {
                    float* op = g_att + (((size_t)(b * T_ + t1)) * J_ + j) * C_ + col;
                    *(float2*)op = make_float2(__uint_as_float(f2tf32(c[nt][0])),
                                               __uint_as_float(f2tf32(c[nt][1])));
                }
                if (t2 < T_) {
                    float* op = g_att + (((size_t)(b * T_ + t2)) * J_ + j) * C_ + col;
                    *(float2*)op = make_float2(__uint_as_float(f2tf32(c[nt][2])),
                                               __uint_as_float(f2tf32(c[nt][3])));
                }
            }
        }
        __syncthreads();
    }
}

// ---------------------------------------------------------------------------
extern "C" void kernel_launch(void* const* d_in, const int* in_sizes, int n_in,
                              void* d_out, int out_size)
{
    const float* x      = (const float*)d_in[0];
    const float* attmap = (const float*)d_in[1];
    const float* weight = (const float*)d_in[2];
    const float* W_qkv  = (const float*)d_in[3];
    const float* W_proj = (const float*)d_in[4];
    const float* b_proj = (const float*)d_in[5];
    float* out = (float*)d_out;

    cudaFuncSetAttribute(mma_gemm,
                         cudaFuncAttributeMaxDynamicSharedMemorySize, GEMM_SMEM);
    cudaFuncSetAttribute(attn_kernel,
                         cudaFuncAttributeMaxDynamicSharedMemorySize, ATTN_SMEM);

    float* gxr;  cudaGetSymbolAddress((void**)&gxr,  g_xr);
    float* gwq;  cudaGetSymbolAddress((void**)&gwq,  g_wq);
    float* gwp;  cudaGetSymbolAddress((void**)&gwp,  g_wp);
    float* gatt; cudaGetSymbolAddress((void**)&gatt, g_att);

    // pre-round GEMM inputs to tf32 (rna) — numerically identical to
    // rounding at smem-staging time, enables cp.async raw copies.
    round4<<<(QSZ/4 + 255)/256, 256>>>(x, gxr, QSZ/4);
    round4<<<(KDIM*1536/4 + 255)/256, 256>>>(W_qkv, gwq, KDIM*1536/4);
    round4<<<(KDIM*512/4 + 255)/256, 256>>>(W_proj, gwp, KDIM*512/4);

    dim3 g1(1536 / 256, (MROWS + 127) / 128);
    mma_gemm<<<g1, 256, GEMM_SMEM>>>(gxr, gwq, nullptr, nullptr, 1536, 0);

    dim3 g2(J_, B_ * H_);
    attn_kernel<<<g2, 512, ATTN_SMEM>>>(attmap, weight);

    dim3 g3(512 / 256, (MROWS + 127) / 128);
    mma_gemm<<<g3, 256, GEMM_SMEM>>>(gatt, gwp, b_proj, out, 512, 1);
}

// round 10
// speedup vs baseline: 4.6238x; 1.1565x over previous
#include <cuda_runtime.h>
#include <cstdint>

#define B_  8
#define T_  243
#define J_  17
#define H_  8
#define HD  64
#define C_  512
#define KDIM 512
#define MROWS (B_*T_*J_)            // 33048
#define QSZ (MROWS*KDIM)            // 16920576

// g_qkv: three row-major [MROWS][512] fp32 matrices; row r=(b*T+t)*J+j, col h*64+d
__device__ float    g_qkv[3*QSZ];
__device__ unsigned g_atth[MROWS*256];   // attention out, half2 words [MROWS][256]
__device__ unsigned g_xh[MROWS*256];     // x as half2 words (k-pairs) [MROWS][256]
__device__ unsigned g_wqh[256*1536];     // W_qkv words [k2][n]
__device__ unsigned g_wph[256*512];      // W_proj words [k2][n]

__device__ __forceinline__ unsigned packh2(float lo, float hi) {
    unsigned r;
    asm("cvt.rn.f16x2.f32 %0, %1, %2;" : "=r"(r) : "f"(hi), "f"(lo));
    return r;
}

__device__ __forceinline__ void mma_f16(
    float& c0, float& c1, float& c2, float& c3,
    unsigned a0, unsigned a1, unsigned a2, unsigned a3,
    unsigned b0, unsigned b1)
{
    asm volatile(
        "mma.sync.aligned.m16n8k16.row.col.f32.f16.f16.f32 "
        "{%0,%1,%2,%3}, {%4,%5,%6,%7}, {%8,%9}, {%0,%1,%2,%3};"
        : "+f"(c0), "+f"(c1), "+f"(c2), "+f"(c3)
        : "r"(a0), "r"(a1), "r"(a2), "r"(a3), "r"(b0), "r"(b1));
}

__device__ __forceinline__ void cp16(uint32_t dst, const void* src, bool ok) {
    int sz = ok ? 16 : 0;
    asm volatile("cp.async.cg.shared.global [%0], [%1], 16, %2;"
                 :: "r"(dst), "l"(src), "r"(sz) : "memory");
}
__device__ __forceinline__ uint32_t smem_u32(const void* p) {
    uint32_t a;
    asm("{ .reg .u64 t; cvta.to.shared.u64 t, %1; cvt.u32.u64 %0, t; }" : "=r"(a) : "l"(p));
    return a;
}

// ---------------------------------------------------------------------------
// prep: pack fp32 -> half2 words
// ---------------------------------------------------------------------------
__global__ void pack_a(const float* __restrict__ in, unsigned* __restrict__ outp, int n4) {
    int i = blockIdx.x * 256 + threadIdx.x;
    if (i < n4) {
        float4 v = ((const float4*)in)[i];
        ((uint2*)outp)[i] = make_uint2(packh2(v.x, v.y), packh2(v.z, v.w));
    }
}
// W [512][N] fp32 -> words [k2][N]: word = (W[2k2][n] lo, W[2k2+1][n] hi)
__global__ void pack_w(const float* __restrict__ W, unsigned* __restrict__ outp,
                       int N, int ntot4) {
    int i = blockIdx.x * 256 + threadIdx.x;
    if (i < ntot4) {
        int n4r = N >> 2;
        int k2 = i / n4r;
        int n  = (i - k2 * n4r) << 2;
        float4 r0 = *(const float4*)(W + (size_t)(2*k2)     * N + n);
        float4 r1 = *(const float4*)(W + (size_t)(2*k2 + 1) * N + n);
        uint4 o = make_uint4(packh2(r0.x, r1.x), packh2(r0.y, r1.y),
                             packh2(r0.z, r1.z), packh2(r0.w, r1.w));
        *(uint4*)(outp + (size_t)k2 * N + n) = o;
    }
}

// ---------------------------------------------------------------------------
// fp16 GEMM, cp.async 3-stage: CTA 128x256, BK=32, 256 threads, 8 warps 64x64.
// A words [128][20] per stage; B words [16][264] per stage.
// mode 0: g_xh @ g_wqh -> g_qkv (fp32, which = col/512)   grid (6, 259)
// mode 1: g_atth @ g_wph + bias -> Cout                   grid (2, 259)
// ---------------------------------------------------------------------------
#define ASTRW 20
#define BSTRW 264
#define ASTAGE_W (128*ASTRW)         // 2560 words
#define BSTAGE_W (16*BSTRW)          // 4224 words
#define STAGE_W  (ASTAGE_W + BSTAGE_W)
#define GEMM_SMEM (3 * STAGE_W * 4)  // 81,408 B

__global__ __launch_bounds__(256, 1) void mma_gemm(
    const unsigned* __restrict__ Aw, const unsigned* __restrict__ Bw,
    const float* __restrict__ bias, float* __restrict__ Cout,
    int N, int mode)
{
    extern __shared__ unsigned smg[];

    int tid  = threadIdx.x;
    int warp = tid >> 5, lane = tid & 31;
    int gid  = lane >> 2, tig = lane & 3;
    int wm   = (warp & 1) * 64;
    int wn   = (warp >> 1) * 64;
    int row0 = blockIdx.y * 128;
    int col0 = blockIdx.x * 256;

    uint32_t smb = smem_u32(smg);
    const unsigned* Abase = Aw + (size_t)row0 * 256;
    const unsigned* Bbase = Bw + col0;

    auto load_stage = [&](int kc, int s) {
        uint32_t Ad = smb + s * STAGE_W * 4;
        uint32_t Bd = Ad + ASTAGE_W * 4;
        // A: 128 rows x 16 words -> 512 cp16 (2/thread)
#pragma unroll
        for (int t = 0; t < 2; t++) {
            int idx = tid + t * 256;
            int r = idx >> 2, cw = idx & 3;
            bool ok = (row0 + r) < MROWS;
            cp16(Ad + (r * ASTRW + cw * 4) * 4,
                 Abase + (size_t)r * 256 + kc * 16 + cw * 4, ok);
        }
        // B: 16 k2-rows x 256 words -> 1024 cp16 (4/thread)
#pragma unroll
        for (int t = 0; t < 4; t++) {
            int idx = tid + t * 256;
            int r = idx >> 6, cw = idx & 63;
            cp16(Bd + (r * BSTRW + cw * 4) * 4,
                 Bbase + (size_t)(kc * 16 + r) * N + cw * 4, true);
        }
        asm volatile("cp.async.commit_group;" ::: "memory");
    };

    float c[4][8][4];
#pragma unroll
    for (int mt = 0; mt < 4; mt++)
#pragma unroll
        for (int nt = 0; nt < 8; nt++)
#pragma unroll
            for (int i = 0; i < 4; i++) c[mt][nt][i] = 0.f;

    const int NITER = KDIM / 32;     // 16
    load_stage(0, 0);
    load_stage(1, 1);

    for (int i = 0; i < NITER; i++) {
        if (i == NITER - 1) asm volatile("cp.async.wait_group 0;" ::: "memory");
        else                asm volatile("cp.async.wait_group 1;" ::: "memory");
        __syncthreads();

        int s = i % 3;
        const unsigned* Ap = smg + s * STAGE_W;
        const unsigned* Bp = Ap + ASTAGE_W;

#pragma unroll
        for (int kk2 = 0; kk2 < 16; kk2 += 8) {     // two k16 steps
            unsigned af[4][4], bf[8][2];
#pragma unroll
            for (int mt = 0; mt < 4; mt++) {
                int m = wm + mt * 16 + gid;
                af[mt][0] = Ap[m * ASTRW + kk2 + tig];
                af[mt][1] = Ap[(m + 8) * ASTRW + kk2 + tig];
                af[mt][2] = Ap[m * ASTRW + kk2 + tig + 4];
                af[mt][3] = Ap[(m + 8) * ASTRW + kk2 + tig + 4];
            }
#pragma unroll
            for (int nt = 0; nt < 8; nt++) {
                int n = wn + nt * 8 + gid;
                bf[nt][0] = Bp[(kk2 + tig) * BSTRW + n];
                bf[nt][1] = Bp[(kk2 + tig + 4) * BSTRW + n];
            }
#pragma unroll
            for (int mt = 0; mt < 4; mt++)
#pragma unroll
                for (int nt = 0; nt < 8; nt++)
                    mma_f16(c[mt][nt][0], c[mt][nt][1], c[mt][nt][2], c[mt][nt][3],
                            af[mt][0], af[mt][1], af[mt][2], af[mt][3],
                            bf[nt][0], bf[nt][1]);
        }

        if (i + 2 < NITER) {
            __syncthreads();
            load_stage(i + 2, (i + 2) % 3);
        }
    }

    if (mode == 0) {
#pragma unroll
        for (int mt = 0; mt < 4; mt++) {
            int rbase = row0 + wm + mt * 16 + gid;
#pragma unroll
            for (int half = 0; half < 2; half++) {
                int r = rbase + half * 8;
                if (r < MROWS) {
#pragma unroll
                    for (int nt = 0; nt < 8; nt++) {
                        int cb = col0 + wn + nt * 8 + 2 * tig;
                        int which = cb >> 9;
                        float* p = g_qkv + (size_t)which * QSZ +
                                   (size_t)r * 512 + (cb & 511);
                        *(float2*)p = half ? make_float2(c[mt][nt][2], c[mt][nt][3])
                                           : make_float2(c[mt][nt][0], c[mt][nt][1]);
                    }
                }
            }
        }
    } else {
#pragma unroll
        for (int mt = 0; mt < 4; mt++) {
            int r1 = row0 + wm + mt * 16 + gid;
            int r2 = r1 + 8;
#pragma unroll
            for (int nt = 0; nt < 8; nt++) {
                int cb = col0 + wn + nt * 8 + 2 * tig;
                float2 bb = *(const float2*)&bias[cb];
                if (r1 < MROWS)
                    *(float2*)&Cout[(size_t)r1 * 512 + cb] =
                        make_float2(c[mt][nt][0] + bb.x, c[mt][nt][1] + bb.y);
                if (r2 < MROWS)
                    *(float2*)&Cout[(size_t)r2 * 512 + cb] =
                        make_float2(c[mt][nt][2] + bb.x, c[mt][nt][3] + bb.y);
            }
        }
    }
}

// ---------------------------------------------------------------------------
// fp16 mma attention. One CTA per (bh, j); 512 threads (16 warps).
// smem (words): kw[32][265] (K, d-pairs), vw[128][72] (V, s-pairs),
//               Qs[64][36] (Q, d-pairs), S fp32 [64][260]
// ---------------------------------------------------------------------------
#define KSTRW 265
#define VSTRW 72
#define QSTRW 36
#define SSTR  260
#define ATTN_SMEM ((32*KSTRW + 128*VSTRW + 64*QSTRW + 64*SSTR) * 4)  // 146,560

__global__ __launch_bounds__(512, 1) void attn_kernel(
    const float* __restrict__ att_map, const float* __restrict__ wptr)
{
    extern __shared__ unsigned smu[];
    unsigned* kw = smu;                  // [32][265]
    unsigned* vw = kw + 32 * KSTRW;      // [128][72]
    unsigned* Qs = vw + 128 * VSTRW;     // [64][36]
    float*    S  = (float*)(Qs + 64 * QSTRW);   // [64][260]

    int tid  = threadIdx.x;
    int warp = tid >> 5, lane = tid & 31;
    int gid  = lane >> 2, tig = lane & 3;

    int j  = blockIdx.x;
    int bh = blockIdx.y;
    int b = bh >> 3, h = bh & 7;

    const size_t JC = (size_t)J_ * C_;
    size_t rowbase = ((size_t)b * T_) * JC + (size_t)j * C_ + h * HD;
    const float* qp0 = g_qkv + rowbase;
    const float* kp0 = g_qkv + (size_t)QSZ + rowbase;
    const float* vp0 = g_qkv + (size_t)2 * QSZ + rowbase;
    float wb = wptr[0];
    float one_minus = 1.f - wb;

    // ---- K: kw[d2][s] = (K[s][2d2], K[s][2d2+1]) ----
    for (int idx = tid; idx < 256 * 32; idx += 512) {
        int s = idx >> 5, d2 = idx & 31;
        float2 kv = (s < T_) ? *(const float2*)(kp0 + (size_t)s * JC + 2 * d2)
                             : make_float2(0.f, 0.f);
        kw[d2 * KSTRW + s] = packh2(kv.x, kv.y);
    }
    // ---- V: vw[s2][d] = (V[2s2][d], V[2s2+1][d]) ----
    for (int idx = tid; idx < 128 * 64; idx += 512) {
        int s2 = idx >> 6, d = idx & 63;
        float v0 = (2 * s2     < T_) ? vp0[(size_t)(2 * s2)     * JC + d] : 0.f;
        float v1 = (2 * s2 + 1 < T_) ? vp0[(size_t)(2 * s2 + 1) * JC + d] : 0.f;
        vw[s2 * VSTRW + d] = packh2(v0, v1);
    }

    for (int rt = 0; rt < 4; rt++) {
        int r0 = rt * 64;
        int rows = min(64, T_ - r0);

        // ---- Q subtile: Qs[t][d2] ----
        for (int idx = tid; idx < 64 * 32; idx += 512) {
            int t = idx >> 5, d2 = idx & 31;
            float2 qv = (t < rows) ? *(const float2*)(qp0 + (size_t)(r0 + t) * JC + 2 * d2)
                                   : make_float2(0.f, 0.f);
            Qs[t * QSTRW + d2] = packh2(qv.x, qv.y);
        }
        __syncthreads();

        // ---- S = Q K^T * 0.125 : warps 2m x 8n (32x32 tiles), k16 x4 ----
        {
            int wm = (warp & 1) * 32;
            int wn = (warp >> 1) * 32;
            float c[2][4][4];
#pragma unroll
            for (int mt = 0; mt < 2; mt++)
#pragma unroll
                for (int nt = 0; nt < 4; nt++)
#pragma unroll
                    for (int i = 0; i < 4; i++) c[mt][nt][i] = 0.f;

#pragma unroll
            for (int kk = 0; kk < 4; kk++) {
                int k2 = kk * 8;
                unsigned a[2][4];
#pragma unroll
                for (int mt = 0; mt < 2; mt++) {
                    int m = wm + mt * 16 + gid;
                    a[mt][0] = Qs[m * QSTRW + k2 + tig];
                    a[mt][1] = Qs[(m + 8) * QSTRW + k2 + tig];
                    a[mt][2] = Qs[m * QSTRW + k2 + tig + 4];
                    a[mt][3] = Qs[(m + 8) * QSTRW + k2 + tig + 4];
                }
#pragma unroll
                for (int nt = 0; nt < 4; nt++) {
                    int n = wn + nt * 8 + gid;
                    unsigned b0 = kw[(k2 + tig) * KSTRW + n];
                    unsigned b1 = kw[(k2 + tig + 4) * KSTRW + n];
#pragma unroll
                    for (int mt = 0; mt < 2; mt++)
                        mma_f16(c[mt][nt][0], c[mt][nt][1], c[mt][nt][2], c[mt][nt][3],
                                a[mt][0], a[mt][1], a[mt][2], a[mt][3], b0, b1);
                }
            }
            const float scale = 0.125f;
#pragma unroll
            for (int mt = 0; mt < 2; mt++) {
                int m = wm + mt * 16 + gid;
#pragma unroll
                for (int nt = 0; nt < 4; nt++) {
                    int n = wn + nt * 8 + 2 * tig;
                    *(float2*)&S[m * SSTR + n] =
                        make_float2(c[mt][nt][0] * scale, c[mt][nt][1] * scale);
                    *(float2*)&S[(m + 8) * SSTR + n] =
                        make_float2(c[mt][nt][2] * scale, c[mt][nt][3] * scale);
                }
            }
        }
        __syncthreads();

        // ---- softmax + blend (att_map prefetched into regs) ----
        for (int r = warp; r < rows; r += 16) {
            float* Sr = S + r * SSTR;
            const float* am = att_map + (((size_t)bh * J_ + j) * T_ + (r0 + r)) * (size_t)T_;
            float amv[8];
#pragma unroll
            for (int i = 0; i < 8; i++) {
                int c2 = lane + 32 * i;
                amv[i] = (c2 < T_) ? am[c2] : 0.f;
            }
            float mx = -1e30f;
            for (int c2 = lane; c2 < T_; c2 += 32) mx = fmaxf(mx, Sr[c2]);
#pragma unroll
            for (int o = 16; o; o >>= 1) mx = fmaxf(mx, __shfl_xor_sync(0xffffffffu, mx, o));
            float sum = 0.f;
            for (int c2 = lane; c2 < T_; c2 += 32) {
                float e = __expf(Sr[c2] - mx);
                Sr[c2] = e;
                sum += e;
            }
#pragma unroll
            for (int o = 16; o; o >>= 1) sum += __shfl_xor_sync(0xffffffffu, sum, o);
            float inv = wb / sum;
#pragma unroll
            for (int i = 0; i < 8; i++) {
                int c2 = lane + 32 * i;
                if (c2 < T_)
                    Sr[c2] = Sr[c2] * inv + one_minus * amv[i];
            }
        }
        __syncthreads();

        // ---- out = S @ V : warps 4m x 4n (16x16 tiles), k16 x16 ----
        {
            int wm = (warp & 3) * 16;
            int wn = (warp >> 2) * 16;
            float c[2][4];
#pragma unroll
            for (int nt = 0; nt < 2; nt++)
#pragma unroll
                for (int i = 0; i < 4; i++) c[nt][i] = 0.f;

#pragma unroll 4
            for (int kk = 0; kk < 16; kk++) {
                int kf = kk * 16;      // float index
                int k2 = kk * 8;       // word row in vw
                int m = wm + gid;
                float2 s0 = *(const float2*)&S[m * SSTR + kf + 2 * tig];
                float2 s1 = *(const float2*)&S[(m + 8) * SSTR + kf + 2 * tig];
                float2 s2 = *(const float2*)&S[m * SSTR + kf + 2 * tig + 8];
                float2 s3 = *(const float2*)&S[(m + 8) * SSTR + kf + 2 * tig + 8];
                unsigned a0 = packh2(s0.x, s0.y);
                unsigned a1 = packh2(s1.x, s1.y);
                unsigned a2 = packh2(s2.x, s2.y);
                unsigned a3 = packh2(s3.x, s3.y);
#pragma unroll
                for (int nt = 0; nt < 2; nt++) {
                    int n = wn + nt * 8 + gid;
                    unsigned b0 = vw[(k2 + tig) * VSTRW + n];
                    unsigned b1 = vw[(k2 + tig + 4) * VSTRW + n];
                    mma_f16(c[nt][0], c[nt][1], c[nt][2], c[nt][3],
                            a0, a1, a2, a3, b0, b1);
                }
            }

            int t1 = r0 + wm + gid;
            int t2 = t1 + 8;
#pragma unroll
            for (int nt = 0; nt < 2; nt++) {
                int wcol = (h * HD + wn + nt * 8) / 2 + tig;
                if (t1 < T_) {
                    size_t r = ((size_t)(b * T_ + t1)) * J_ + j;
                    g_atth[r * 256 + wcol] = packh2(c[nt][0], c[nt][1]);
                }
                if (t2 < T_) {
                    size_t r = ((size_t)(b * T_ + t2)) * J_ + j;
                    g_atth[r * 256 + wcol] = packh2(c[nt][2], c[nt][3]);
                }
            }
        }
        __syncthreads();
    }
}

// ---------------------------------------------------------------------------
extern "C" void kernel_launch(void* const* d_in, const int* in_sizes, int n_in,
                              void* d_out, int out_size)
{
    const float* x      = (const float*)d_in[0];
    const float* attmap = (const float*)d_in[1];
    const float* weight = (const float*)d_in[2];
    const float* W_qkv  = (const float*)d_in[3];
    const float* W_proj = (const float*)d_in[4];
    const float* b_proj = (const float*)d_in[5];
    float* out = (float*)d_out;

    cudaFuncSetAttribute(mma_gemm,
                         cudaFuncAttributeMaxDynamicSharedMemorySize, GEMM_SMEM);
    cudaFuncSetAttribute(attn_kernel,
                         cudaFuncAttributeMaxDynamicSharedMemorySize, ATTN_SMEM);

    unsigned *gxh, *gwq, *gwp, *gat;
    cudaGetSymbolAddress((void**)&gxh, g_xh);
    cudaGetSymbolAddress((void**)&gwq, g_wqh);
    cudaGetSymbolAddress((void**)&gwp, g_wph);
    cudaGetSymbolAddress((void**)&gat, g_atth);

    pack_a<<<(QSZ/4 + 255)/256, 256>>>(x, gxh, QSZ/4);
    pack_w<<<(256*384 + 255)/256, 256>>>(W_qkv, gwq, 1536, 256*384);
    pack_w<<<(256*128 + 255)/256, 256>>>(W_proj, gwp, 512, 256*128);

    dim3 g1(1536 / 256, (MROWS + 127) / 128);
    mma_gemm<<<g1, 256, GEMM_SMEM>>>(gxh, gwq, nullptr, nullptr, 1536, 0);

    dim3 g2(J_, B_ * H_);
    attn_kernel<<<g2, 512, ATTN_SMEM>>>(attmap, weight);

    dim3 g3(512 / 256, (MROWS + 127) / 128);
    mma_gemm<<<g3, 256, GEMM_SMEM>>>(gat, gwp, b_proj, out, 512, 1);
}

// round 11
// speedup vs baseline: 5.2157x; 1.1280x over previous
#include <cuda_runtime.h>
#include <cstdint>

#define B_  8
#define T_  243
#define J_  17
#define H_  8
#define HD  64
#define C_  512
#define KDIM 512
#define MROWS (B_*T_*J_)            // 33048
#define QSZ (MROWS*KDIM)

// packed half2 storage: q/k/v as 3 x [MROWS][256] words; row r=(b*T+t)*J+j
__device__ unsigned g_qkvh[3*MROWS*256];
__device__ unsigned g_atth[MROWS*256];   // attention out words
__device__ unsigned g_xh[MROWS*256];     // x as half2 k-pair words
__device__ unsigned g_wqh[256*1536];     // W_qkv words [k2][n]
__device__ unsigned g_wph[256*512];      // W_proj words [k2][n]

__device__ __forceinline__ unsigned packh2(float lo, float hi) {
    unsigned r;
    asm("cvt.rn.f16x2.f32 %0, %1, %2;" : "=r"(r) : "f"(hi), "f"(lo));
    return r;
}
__device__ __forceinline__ unsigned prmt(unsigned a, unsigned b, unsigned sel) {
    unsigned r;
    asm("prmt.b32 %0, %1, %2, %3;" : "=r"(r) : "r"(a), "r"(b), "r"(sel));
    return r;
}

__device__ __forceinline__ void mma_f16(
    float& c0, float& c1, float& c2, float& c3,
    unsigned a0, unsigned a1, unsigned a2, unsigned a3,
    unsigned b0, unsigned b1)
{
    asm volatile(
        "mma.sync.aligned.m16n8k16.row.col.f32.f16.f16.f32 "
        "{%0,%1,%2,%3}, {%4,%5,%6,%7}, {%8,%9}, {%0,%1,%2,%3};"
        : "+f"(c0), "+f"(c1), "+f"(c2), "+f"(c3)
        : "r"(a0), "r"(a1), "r"(a2), "r"(a3), "r"(b0), "r"(b1));
}

__device__ __forceinline__ void cp16(uint32_t dst, const void* src, bool ok) {
    int sz = ok ? 16 : 0;
    asm volatile("cp.async.cg.shared.global [%0], [%1], 16, %2;"
                 :: "r"(dst), "l"(src), "r"(sz) : "memory");
}
__device__ __forceinline__ uint32_t smem_u32(const void* p) {
    uint32_t a;
    asm("{ .reg .u64 t; cvta.to.shared.u64 t, %1; cvt.u32.u64 %0, t; }" : "=r"(a) : "l"(p));
    return a;
}

// ---------------------------------------------------------------------------
// prep: pack fp32 -> half2 words
// ---------------------------------------------------------------------------
__global__ void pack_a(const float* __restrict__ in, unsigned* __restrict__ outp, int n4) {
    int i = blockIdx.x * 256 + threadIdx.x;
    if (i < n4) {
        float4 v = ((const float4*)in)[i];
        ((uint2*)outp)[i] = make_uint2(packh2(v.x, v.y), packh2(v.z, v.w));
    }
}
__global__ void pack_w(const float* __restrict__ W, unsigned* __restrict__ outp,
                       int N, int ntot4) {
    int i = blockIdx.x * 256 + threadIdx.x;
    if (i < ntot4) {
        int n4r = N >> 2;
        int k2 = i / n4r;
        int n  = (i - k2 * n4r) << 2;
        float4 r0 = *(const float4*)(W + (size_t)(2*k2)     * N + n);
        float4 r1 = *(const float4*)(W + (size_t)(2*k2 + 1) * N + n);
        uint4 o = make_uint4(packh2(r0.x, r1.x), packh2(r0.y, r1.y),
                             packh2(r0.z, r1.z), packh2(r0.w, r1.w));
        *(uint4*)(outp + (size_t)k2 * N + n) = o;
    }
}

// ---------------------------------------------------------------------------
// fp16 GEMM, cp.async 3-stage: CTA 128x256, BK=32, 256 threads, 8 warps 64x64.
// mode 0: g_xh @ g_wqh -> g_qkvh words     grid (6, 259)
// mode 1: g_atth @ g_wph + bias -> Cout    grid (2, 259)
// ---------------------------------------------------------------------------
#define ASTRW 20
#define BSTRW 264
#define ASTAGE_W (128*ASTRW)
#define BSTAGE_W (16*BSTRW)
#define STAGE_W  (ASTAGE_W + BSTAGE_W)
#define GEMM_SMEM (3 * STAGE_W * 4)  // 81,408 B

__global__ __launch_bounds__(256, 1) void mma_gemm(
    const unsigned* __restrict__ Aw, const unsigned* __restrict__ Bw,
    const float* __restrict__ bias, float* __restrict__ Cout,
    int N, int mode)
{
    extern __shared__ unsigned smg[];

    int tid  = threadIdx.x;
    int warp = tid >> 5, lane = tid & 31;
    int gid  = lane >> 2, tig = lane & 3;
    int wm   = (warp & 1) * 64;
    int wn   = (warp >> 1) * 64;
    int row0 = blockIdx.y * 128;
    int col0 = blockIdx.x * 256;

    uint32_t smb = smem_u32(smg);
    const unsigned* Abase = Aw + (size_t)row0 * 256;
    const unsigned* Bbase = Bw + col0;

    auto load_stage = [&](int kc, int s) {
        uint32_t Ad = smb + s * STAGE_W * 4;
        uint32_t Bd = Ad + ASTAGE_W * 4;
#pragma unroll
        for (int t = 0; t < 2; t++) {
            int idx = tid + t * 256;
            int r = idx >> 2, cw = idx & 3;
            bool ok = (row0 + r) < MROWS;
            cp16(Ad + (r * ASTRW + cw * 4) * 4,
                 Abase + (size_t)r * 256 + kc * 16 + cw * 4, ok);
        }
#pragma unroll
        for (int t = 0; t < 4; t++) {
            int idx = tid + t * 256;
            int r = idx >> 6, cw = idx & 63;
            cp16(Bd + (r * BSTRW + cw * 4) * 4,
                 Bbase + (size_t)(kc * 16 + r) * N + cw * 4, true);
        }
        asm volatile("cp.async.commit_group;" ::: "memory");
    };

    float c[4][8][4];
#pragma unroll
    for (int mt = 0; mt < 4; mt++)
#pragma unroll
        for (int nt = 0; nt < 8; nt++)
#pragma unroll
            for (int i = 0; i < 4; i++) c[mt][nt][i] = 0.f;

    const int NITER = KDIM / 32;
    load_stage(0, 0);
    load_stage(1, 1);

    for (int i = 0; i < NITER; i++) {
        if (i == NITER - 1) asm volatile("cp.async.wait_group 0;" ::: "memory");
        else                asm volatile("cp.async.wait_group 1;" ::: "memory");
        __syncthreads();

        int s = i % 3;
        const unsigned* Ap = smg + s * STAGE_W;
        const unsigned* Bp = Ap + ASTAGE_W;

#pragma unroll
        for (int kk2 = 0; kk2 < 16; kk2 += 8) {
            unsigned af[4][4], bf[8][2];
#pragma unroll
            for (int mt = 0; mt < 4; mt++) {
                int m = wm + mt * 16 + gid;
                af[mt][0] = Ap[m * ASTRW + kk2 + tig];
                af[mt][1] = Ap[(m + 8) * ASTRW + kk2 + tig];
                af[mt][2] = Ap[m * ASTRW + kk2 + tig + 4];
                af[mt][3] = Ap[(m + 8) * ASTRW + kk2 + tig + 4];
            }
#pragma unroll
            for (int nt = 0; nt < 8; nt++) {
                int n = wn + nt * 8 + gid;
                bf[nt][0] = Bp[(kk2 + tig) * BSTRW + n];
                bf[nt][1] = Bp[(kk2 + tig + 4) * BSTRW + n];
            }
#pragma unroll
            for (int mt = 0; mt < 4; mt++)
#pragma unroll
                for (int nt = 0; nt < 8; nt++)
                    mma_f16(c[mt][nt][0], c[mt][nt][1], c[mt][nt][2], c[mt][nt][3],
                            af[mt][0], af[mt][1], af[mt][2], af[mt][3],
                            bf[nt][0], bf[nt][1]);
        }

        if (i + 2 < NITER) {
            __syncthreads();
            load_stage(i + 2, (i + 2) % 3);
        }
    }

    if (mode == 0) {
        // pack adjacent-column pairs to half2 words in g_qkvh
#pragma unroll
        for (int mt = 0; mt < 4; mt++) {
            int rbase = row0 + wm + mt * 16 + gid;
#pragma unroll
            for (int half = 0; half < 2; half++) {
                int r = rbase + half * 8;
                if (r < MROWS) {
#pragma unroll
                    for (int nt = 0; nt < 8; nt++) {
                        int cb = col0 + wn + nt * 8 + 2 * tig;
                        int which = cb >> 9;
                        int wcol = (cb & 511) >> 1;
                        unsigned w = half ? packh2(c[mt][nt][2], c[mt][nt][3])
                                          : packh2(c[mt][nt][0], c[mt][nt][1]);
                        g_qkvh[(size_t)which * (MROWS*256) + (size_t)r * 256 + wcol] = w;
                    }
                }
            }
        }
    } else {
#pragma unroll
        for (int mt = 0; mt < 4; mt++) {
            int r1 = row0 + wm + mt * 16 + gid;
            int r2 = r1 + 8;
#pragma unroll
            for (int nt = 0; nt < 8; nt++) {
                int cb = col0 + wn + nt * 8 + 2 * tig;
                float2 bb = *(const float2*)&bias[cb];
                if (r1 < MROWS)
                    *(float2*)&Cout[(size_t)r1 * 512 + cb] =
                        make_float2(c[mt][nt][0] + bb.x, c[mt][nt][1] + bb.y);
                if (r2 < MROWS)
                    *(float2*)&Cout[(size_t)r2 * 512 + cb] =
                        make_float2(c[mt][nt][2] + bb.x, c[mt][nt][3] + bb.y);
            }
        }
    }
}

// ---------------------------------------------------------------------------
// fp16 attention, packed-word I/O. One CTA per (bh, j); 512 threads.
// smem words: kw[32][265], vw[128][72], Qs[64][36]; S fp32 [64][260]
// (S rows are overwritten in place with packed half2 words by the softmax)
// ---------------------------------------------------------------------------
#define KSTRW 265
#define VSTRW 72
#define QSTRW 36
#define SSTR  260
#define ATTN_SMEM ((32*KSTRW + 128*VSTRW + 64*QSTRW + 64*SSTR) * 4)  // 146,560

__global__ __launch_bounds__(512, 1) void attn_kernel(
    const float* __restrict__ att_map, const float* __restrict__ wptr)
{
    extern __shared__ unsigned smu[];
    unsigned* kw = smu;
    unsigned* vw = kw + 32 * KSTRW;
    unsigned* Qs = vw + 128 * VSTRW;
    float*    S  = (float*)(Qs + 64 * QSTRW);

    int tid  = threadIdx.x;
    int warp = tid >> 5, lane = tid & 31;
    int gid  = lane >> 2, tig = lane & 3;

    int j  = blockIdx.x;
    int bh = blockIdx.y;
    int b = bh >> 3, h = bh & 7;

    const int JW = J_ * 256;
    size_t rowbase = ((size_t)b * T_) * JW + (size_t)j * 256 + h * 32;
    const unsigned* qh = g_qkvh + rowbase;
    const unsigned* kh = g_qkvh + (size_t)(MROWS*256) + rowbase;
    const unsigned* vh = g_qkvh + (size_t)2 * (MROWS*256) + rowbase;
    float wb = wptr[0];
    float one_minus = 1.f - wb;

    // ---- K: kw[d2][s] <- word copy (transposed) ----
    for (int idx = tid; idx < 256 * 32; idx += 512) {
        int s = idx >> 5, d2 = idx & 31;
        unsigned w = (s < T_) ? kh[(size_t)s * JW + d2] : 0u;
        kw[d2 * KSTRW + s] = w;
    }
    // ---- V: s-pair words via prmt ----
    for (int idx = tid; idx < 128 * 32; idx += 512) {
        int s2 = idx >> 5, d2 = idx & 31;
        unsigned w0 = (2 * s2     < T_) ? vh[(size_t)(2 * s2)     * JW + d2] : 0u;
        unsigned w1 = (2 * s2 + 1 < T_) ? vh[(size_t)(2 * s2 + 1) * JW + d2] : 0u;
        vw[s2 * VSTRW + 2 * d2]     = prmt(w0, w1, 0x5410);
        vw[s2 * VSTRW + 2 * d2 + 1] = prmt(w0, w1, 0x7632);
    }

    for (int rt = 0; rt < 4; rt++) {
        int r0 = rt * 64;
        int rows = min(64, T_ - r0);

        // ---- Q subtile: word copy ----
        for (int idx = tid; idx < 64 * 32; idx += 512) {
            int t = idx >> 5, d2 = idx & 31;
            Qs[t * QSTRW + d2] = (t < rows) ? qh[(size_t)(r0 + t) * JW + d2] : 0u;
        }
        __syncthreads();

        // ---- S = Q K^T * 0.125 : warps 2m x 8n (32x32 tiles) ----
        {
            int wm = (warp & 1) * 32;
            int wn = (warp >> 1) * 32;
            float c[2][4][4];
#pragma unroll
            for (int mt = 0; mt < 2; mt++)
#pragma unroll
                for (int nt = 0; nt < 4; nt++)
#pragma unroll
                    for (int i = 0; i < 4; i++) c[mt][nt][i] = 0.f;

#pragma unroll
            for (int kk = 0; kk < 4; kk++) {
                int k2 = kk * 8;
                unsigned a[2][4];
#pragma unroll
                for (int mt = 0; mt < 2; mt++) {
                    int m = wm + mt * 16 + gid;
                    a[mt][0] = Qs[m * QSTRW + k2 + tig];
                    a[mt][1] = Qs[(m + 8) * QSTRW + k2 + tig];
                    a[mt][2] = Qs[m * QSTRW + k2 + tig + 4];
                    a[mt][3] = Qs[(m + 8) * QSTRW + k2 + tig + 4];
                }
#pragma unroll
                for (int nt = 0; nt < 4; nt++) {
                    int n = wn + nt * 8 + gid;
                    unsigned b0 = kw[(k2 + tig) * KSTRW + n];
                    unsigned b1 = kw[(k2 + tig + 4) * KSTRW + n];
#pragma unroll
                    for (int mt = 0; mt < 2; mt++)
                        mma_f16(c[mt][nt][0], c[mt][nt][1], c[mt][nt][2], c[mt][nt][3],
                                a[mt][0], a[mt][1], a[mt][2], a[mt][3], b0, b1);
                }
            }
            const float scale = 0.125f;
#pragma unroll
            for (int mt = 0; mt < 2; mt++) {
                int m = wm + mt * 16 + gid;
#pragma unroll
                for (int nt = 0; nt < 4; nt++) {
                    int n = wn + nt * 8 + 2 * tig;
                    *(float2*)&S[m * SSTR + n] =
                        make_float2(c[mt][nt][0] * scale, c[mt][nt][1] * scale);
                    *(float2*)&S[(m + 8) * SSTR + n] =
                        make_float2(c[mt][nt][2] * scale, c[mt][nt][3] * scale);
                }
            }
        }
        __syncthreads();

        // ---- softmax + blend; emit packed half2 words in place ----
        for (int r = warp; r < rows; r += 16) {
            float* Sr = S + r * SSTR;
            unsigned* Srw = (unsigned*)Sr;
            const float* am = att_map + (((size_t)bh * J_ + j) * T_ + (r0 + r)) * (size_t)T_;
            float v0[4], v1[4], a0[4], a1[4];
#pragma unroll
            for (int i = 0; i < 4; i++) {
                int c0 = 2 * lane + 64 * i;
                bool ok0 = c0 < T_, ok1 = c0 + 1 < T_;
                v0[i] = ok0 ? Sr[c0]     : -1e30f;
                v1[i] = ok1 ? Sr[c0 + 1] : -1e30f;
                a0[i] = ok0 ? am[c0]     : 0.f;
                a1[i] = ok1 ? am[c0 + 1] : 0.f;
            }
            float mx = -1e30f;
#pragma unroll
            for (int i = 0; i < 4; i++) mx = fmaxf(mx, fmaxf(v0[i], v1[i]));
#pragma unroll
            for (int o = 16; o; o >>= 1) mx = fmaxf(mx, __shfl_xor_sync(0xffffffffu, mx, o));
            float sum = 0.f;
#pragma unroll
            for (int i = 0; i < 4; i++) {
                v0[i] = __expf(v0[i] - mx);
                v1[i] = __expf(v1[i] - mx);
                sum += v0[i] + v1[i];
            }
#pragma unroll
            for (int o = 16; o; o >>= 1) sum += __shfl_xor_sync(0xffffffffu, sum, o);
            float inv = wb / sum;
#pragma unroll
            for (int i = 0; i < 4; i++) {
                int c0 = 2 * lane + 64 * i;
                float f0 = (c0     < T_) ? v0[i] * inv + one_minus * a0[i] : 0.f;
                float f1 = (c0 + 1 < T_) ? v1[i] * inv + one_minus * a1[i] : 0.f;
                Srw[lane + 32 * i] = packh2(f0, f1);
            }
        }
        __syncthreads();

        // ---- out = S @ V : warps 4m x 4n (16x16 tiles), word A-frags ----
        {
            int wm = (warp & 3) * 16;
            int wn = (warp >> 2) * 16;
            const unsigned* Sw = (const unsigned*)S;
            float c[2][4];
#pragma unroll
            for (int nt = 0; nt < 2; nt++)
#pragma unroll
                for (int i = 0; i < 4; i++) c[nt][i] = 0.f;

#pragma unroll 4
            for (int kk = 0; kk < 16; kk++) {
                int k2 = kk * 8;
                int m = wm + gid;
                unsigned a0 = Sw[m * SSTR + k2 + tig];
                unsigned a1 = Sw[(m + 8) * SSTR + k2 + tig];
                unsigned a2 = Sw[m * SSTR + k2 + tig + 4];
                unsigned a3 = Sw[(m + 8) * SSTR + k2 + tig + 4];
#pragma unroll
                for (int nt = 0; nt < 2; nt++) {
                    int n = wn + nt * 8 + gid;
                    unsigned b0 = vw[(k2 + tig) * VSTRW + n];
                    unsigned b1 = vw[(k2 + tig + 4) * VSTRW + n];
                    mma_f16(c[nt][0], c[nt][1], c[nt][2], c[nt][3],
                            a0, a1, a2, a3, b0, b1);
                }
            }

            int t1 = r0 + wm + gid;
            int t2 = t1 + 8;
#pragma unroll
            for (int nt = 0; nt < 2; nt++) {
                int wcol = (h * HD + wn + nt * 8) / 2 + tig;
                if (t1 < T_) {
                    size_t r = ((size_t)(b * T_ + t1)) * J_ + j;
                    g_atth[r * 256 + wcol] = packh2(c[nt][0], c[nt][1]);
                }
                if (t2 < T_) {
                    size_t r = ((size_t)(b * T_ + t2)) * J_ + j;
                    g_atth[r * 256 + wcol] = packh2(c[nt][2], c[nt][3]);
                }
            }
        }
        __syncthreads();
    }
}

// ---------------------------------------------------------------------------
extern "C" void kernel_launch(void* const* d_in, const int* in_sizes, int n_in,
                              void* d_out, int out_size)
{
    const float* x      = (const float*)d_in[0];
    const float* attmap = (const float*)d_in[1];
    const float* weight = (const float*)d_in[2];
    const float* W_qkv  = (const float*)d_in[3];
    const float* W_proj = (const float*)d_in[4];
    const float* b_proj = (const float*)d_in[5];
    float* out = (float*)d_out;

    cudaFuncSetAttribute(mma_gemm,
                         cudaFuncAttributeMaxDynamicSharedMemorySize, GEMM_SMEM);
    cudaFuncSetAttribute(attn_kernel,
                         cudaFuncAttributeMaxDynamicSharedMemorySize, ATTN_SMEM);

    unsigned *gxh, *gwq, *gwp, *gat;
    cudaGetSymbolAddress((void**)&gxh, g_xh);
    cudaGetSymbolAddress((void**)&gwq, g_wqh);
    cudaGetSymbolAddress((void**)&gwp, g_wph);
    cudaGetSymbolAddress((void**)&gat, g_atth);

    pack_a<<<(QSZ/4 + 255)/256, 256>>>(x, gxh, QSZ/4);
    pack_w<<<(256*384 + 255)/256, 256>>>(W_qkv, gwq, 1536, 256*384);
    pack_w<<<(256*128 + 255)/256, 256>>>(W_proj, gwp, 512, 256*128);

    dim3 g1(1536 / 256, (MROWS + 127) / 128);
    mma_gemm<<<g1, 256, GEMM_SMEM>>>(gxh, gwq, nullptr, nullptr, 1536, 0);

    dim3 g2(J_, B_ * H_);
    attn_kernel<<<g2, 512, ATTN_SMEM>>>(attmap, weight);

    dim3 g3(512 / 256, (MROWS + 127) / 128);
    mma_gemm<<<g3, 256, GEMM_SMEM>>>(gat, gwp, b_proj, out, 512, 1);
}